// round 9
// baseline (speedup 1.0000x reference)
#include <cuda_runtime.h>
#include <math.h>
#include <cstdint>

#define CH    64
#define HW    4096
#define NB    4
#define CHW   (CH*HW)
#define TOTAL (NB*CHW)

typedef unsigned long long ull;
typedef unsigned int       u32;
typedef unsigned short     u16;

// ------------------------- device scratch ----------------------------------
__device__ __align__(16) float g_yq[TOTAL];   // [n][c][p]
__device__ __align__(16) float g_yk[TOTAL];
__device__ float               g_aff[4*CH];
__device__ __align__(16) u16   g_gh[TOTAL];   // gated value hi/lo bf16 [n][c][p]
__device__ __align__(16) u16   g_gl[TOTAL];
__device__ __align__(16) u16   g_qh[TOTAL];   // Q' hi/lo bf16 [n][p][c]
__device__ __align__(16) u16   g_ql[TOTAL];
__device__ __align__(16) u16   g_kh[TOTAL];   // K' hi/lo bf16 [n][p][c]
__device__ __align__(16) u16   g_kl[TOTAL];
// attention partials: [n][kh][qt] -> 128q x 64c, plus denominators
__device__ __align__(16) float g_pctx[2*NB*32*8192];
__device__ __align__(16) float g_pden[2*NB*4096];

// ------------------------------ helpers ------------------------------------
__device__ __forceinline__ ull pk2(float x, float y) {
    ull r; asm("mov.b64 %0,{%1,%2};" : "=l"(r) : "f"(x), "f"(y)); return r;
}
__device__ __forceinline__ void upk2(ull v, float& x, float& y) {
    asm("mov.b64 {%0,%1},%2;" : "=f"(x), "=f"(y) : "l"(v));
}
__device__ __forceinline__ void fma2(ull& d, ull a, ull b) {
    asm("fma.rn.f32x2 %0,%1,%2,%0;" : "+l"(d) : "l"(a), "l"(b));
}
__device__ __forceinline__ ull add2_(ull a, ull b) {
    ull r; asm("add.rn.f32x2 %0,%1,%2;" : "=l"(r) : "l"(a), "l"(b)); return r;
}
__device__ __forceinline__ ull mul2_(ull a, ull b) {
    ull r; asm("mul.rn.f32x2 %0,%1,%2;" : "=l"(r) : "l"(a), "l"(b)); return r;
}
__device__ __forceinline__ ull ld2(const float* p) { return *reinterpret_cast<const ull*>(p); }

// split fp32 pair (a,b) -> bf16x2 hi + bf16x2 lo (low 16 bits = a)
__device__ __forceinline__ void split2(float a, float b, u32& h2, u32& l2) {
    asm("cvt.rn.bf16x2.f32 %0, %1, %2;" : "=r"(h2) : "f"(b), "f"(a));
    float fa = __uint_as_float(h2 << 16);
    float fb = __uint_as_float(h2 & 0xffff0000u);
    asm("cvt.rn.bf16x2.f32 %0, %1, %2;" : "=r"(l2) : "f"(b - fb), "f"(a - fa));
}
__device__ __forceinline__ u32 smem_u32(const void* p) {
    u32 a; asm("{ .reg .u64 t; cvta.to.shared.u64 t, %1; cvt.u32.u64 %0, t; }" : "=r"(a) : "l"(p));
    return a;
}
__device__ __forceinline__ void cpasync16(u32 s, const void* g) {
    asm volatile("cp.async.cg.shared.global [%0], [%1], 16;" :: "r"(s), "l"(g) : "memory");
}
#define CP_COMMIT() asm volatile("cp.async.commit_group;" ::: "memory")
#define CP_WAIT(n)  asm volatile("cp.async.wait_group %0;" :: "n"(n) : "memory")

__device__ __forceinline__ void ldsm4(u32* t, u32 addr) {
    asm volatile("ldmatrix.sync.aligned.m8n8.x4.shared.b16 {%0,%1,%2,%3}, [%4];"
        : "=r"(t[0]), "=r"(t[1]), "=r"(t[2]), "=r"(t[3]) : "r"(addr));
}
__device__ __forceinline__ void mma16816(float* d, const u32* a, u32 b0, u32 b1) {
    asm volatile("mma.sync.aligned.m16n8k16.row.col.f32.bf16.bf16.f32 "
        "{%0,%1,%2,%3}, {%4,%5,%6,%7}, {%8,%9}, {%0,%1,%2,%3};"
        : "+f"(d[0]), "+f"(d[1]), "+f"(d[2]), "+f"(d[3])
        : "r"(a[0]), "r"(a[1]), "r"(a[2]), "r"(a[3]), "r"(b0), "r"(b1));
}

// ---------------------------------------------------------------------------
// Kernel 1: projections + gated value bf16 split. grid 512, 32 positions/blk
// ---------------------------------------------------------------------------
__global__ __launch_bounds__(256)
void proj_kernel(const float* __restrict__ x,
                 const float* __restrict__ h0,
                 const float* __restrict__ h1,
                 const float* __restrict__ Wq, const float* __restrict__ bq,
                 const float* __restrict__ Wk, const float* __restrict__ bk,
                 const float* __restrict__ Wv, const float* __restrict__ bv) {
    extern __shared__ float sm[];
    float* sWq = sm;
    float* sWk = sm + 4096;
    float* sWv = sm + 8192;
    float* xs  = sm + 12288;   // [64][32]

    int tid = threadIdx.x;
    for (int i = tid; i < 4096; i += 256) {
        sWq[i] = Wq[i]; sWk[i] = Wk[i]; sWv[i] = Wv[i];
    }
    int P0 = blockIdx.x * 32;
    int n  = P0 >> 12;
    int p0 = P0 & (HW - 1);
    const float* xb = x + (size_t)n*CHW + p0;
    for (int i = tid; i < 2048; i += 256) {
        int c = i >> 5, pp = i & 31;
        xs[c*32 + pp] = xb[(size_t)c*HW + pp];
    }
    __syncthreads();

    int ty = tid >> 4, tx = tid & 15;
    ull aq2[4], ak2[4], av2[4];
    #pragma unroll
    for (int io = 0; io < 4; io++) {
        int o = ty + 16*io;
        aq2[io] = pk2(bq[o], bq[o]);
        ak2[io] = pk2(bk[o], bk[o]);
        av2[io] = pk2(bv[o], bv[o]);
    }
    #pragma unroll 4
    for (int c = 0; c < 64; c++) {
        ull xv = ld2(&xs[c*32 + 2*tx]);
        #pragma unroll
        for (int io = 0; io < 4; io++) {
            int o = ty + 16*io;
            float wqs = sWq[o*64+c], wks = sWk[o*64+c], wvs = sWv[o*64+c];
            fma2(aq2[io], pk2(wqs,wqs), xv);
            fma2(ak2[io], pk2(wks,wks), xv);
            fma2(av2[io], pk2(wvs,wvs), xv);
        }
    }
    size_t base = (size_t)n*CHW + p0;
    #pragma unroll
    for (int io = 0; io < 4; io++) {
        int o = ty + 16*io;
        size_t idx = base + (size_t)o*HW + 2*tx;
        *reinterpret_cast<ull*>(&g_yq[idx]) = aq2[io];
        *reinterpret_cast<ull*>(&g_yk[idx]) = ak2[io];
        ull h0p = *reinterpret_cast<const ull*>(&h0[idx]);
        ull h1p = *reinterpret_cast<const ull*>(&h1[idx]);
        ull gv  = mul2_(add2_(h0p, h1p), av2[io]);
        float ga, gb; upk2(gv, ga, gb);
        u32 h2, l2; split2(ga, gb, h2, l2);
        *reinterpret_cast<u32*>(&g_gh[idx]) = h2;
        *reinterpret_cast<u32*>(&g_gl[idx]) = l2;
    }
}

// ---------------------------------------------------------------------------
// Kernel 2: BN stats -> affine coefs
// ---------------------------------------------------------------------------
__global__ __launch_bounds__(256)
void stats_kernel(const float* __restrict__ gq, const float* __restrict__ betaq,
                  const float* __restrict__ gk, const float* __restrict__ betak) {
    int ch    = blockIdx.x & 63;
    int which = blockIdx.x >> 6;
    const float* y = which ? g_yk : g_yq;
    int tid = threadIdx.x;
    float s = 0.f, sq = 0.f;
    for (int n = 0; n < NB; n++) {
        const float4* row = (const float4*)(y + (size_t)n*CHW + (size_t)ch*HW);
        for (int p = tid; p < 1024; p += 256) {
            float4 v = row[p];
            s  += (v.x + v.y) + (v.z + v.w);
            sq += (v.x*v.x + v.y*v.y) + (v.z*v.z + v.w*v.w);
        }
    }
    __shared__ float rs[256], rq[256];
    rs[tid] = s; rq[tid] = sq;
    __syncthreads();
    for (int st = 128; st > 0; st >>= 1) {
        if (tid < st) { rs[tid] += rs[tid+st]; rq[tid] += rq[tid+st]; }
        __syncthreads();
    }
    if (tid == 0) {
        const float invn = 1.0f / (NB * HW);
        float mean = rs[0] * invn;
        float var  = rq[0] * invn - mean*mean;
        float g = which ? gk[ch]    : gq[ch];
        float b = which ? betak[ch] : betaq[ch];
        float a = g * rsqrtf(var + 1e-5f);
        g_aff[which*128 + ch]      = a;
        g_aff[which*128 + 64 + ch] = b - mean*a;
    }
}

// ---------------------------------------------------------------------------
// Kernel 2.5: BN affine + relu, bf16 split, transpose [n][c][p] -> [n][p][c]
// ---------------------------------------------------------------------------
__global__ __launch_bounds__(256)
void prep_kernel() {
    extern __shared__ u16 sp[];
    u16* sQh = sp;
    u16* sQl = sp + 8384;
    u16* sKh = sp + 16768;
    u16* sKl = sp + 25152;
    int tid = threadIdx.x;
    int n = blockIdx.y, p0 = blockIdx.x * 128;
    size_t nb = (size_t)n*CHW;

    for (int i = tid; i < 2048; i += 256) {
        int c = i >> 5, j = i & 31;
        float4 vq = *(const float4*)&g_yq[nb + (size_t)c*HW + p0 + 4*j];
        float4 vk = *(const float4*)&g_yk[nb + (size_t)c*HW + p0 + 4*j];
        float aq = g_aff[c], bqv = g_aff[64+c];
        float ak = g_aff[128+c], bkv = g_aff[192+c];
        float q0f = fmaxf(0.f, aq*vq.x + bqv), q1f = fmaxf(0.f, aq*vq.y + bqv);
        float q2f = fmaxf(0.f, aq*vq.z + bqv), q3f = fmaxf(0.f, aq*vq.w + bqv);
        float k0f = fmaxf(0.f, ak*vk.x + bkv), k1f = fmaxf(0.f, ak*vk.y + bkv);
        float k2f = fmaxf(0.f, ak*vk.z + bkv), k3f = fmaxf(0.f, ak*vk.w + bkv);
        int base = c*131 + 4*j;
        u32 h2, l2;
        split2(q0f, q1f, h2, l2);
        sQh[base]   = (u16)h2; sQh[base+1] = (u16)(h2>>16);
        sQl[base]   = (u16)l2; sQl[base+1] = (u16)(l2>>16);
        split2(q2f, q3f, h2, l2);
        sQh[base+2] = (u16)h2; sQh[base+3] = (u16)(h2>>16);
        sQl[base+2] = (u16)l2; sQl[base+3] = (u16)(l2>>16);
        split2(k0f, k1f, h2, l2);
        sKh[base]   = (u16)h2; sKh[base+1] = (u16)(h2>>16);
        sKl[base]   = (u16)l2; sKl[base+1] = (u16)(l2>>16);
        split2(k2f, k3f, h2, l2);
        sKh[base+2] = (u16)h2; sKh[base+3] = (u16)(h2>>16);
        sKl[base+2] = (u16)l2; sKl[base+3] = (u16)(l2>>16);
    }
    __syncthreads();

    u32* oqh = (u32*)g_qh; u32* oql = (u32*)g_ql;
    u32* okh = (u32*)g_kh; u32* okl = (u32*)g_kl;
    for (int i = tid; i < 4096; i += 256) {
        int p = i >> 5, c2 = i & 31;
        u32 idx = (u32)(n*4096 + p0 + p)*32 + c2;
        u32 a, b;
        a = sQh[(2*c2)*131 + p]; b = sQh[(2*c2+1)*131 + p]; oqh[idx] = a | (b<<16);
        a = sQl[(2*c2)*131 + p]; b = sQl[(2*c2+1)*131 + p]; oql[idx] = a | (b<<16);
        a = sKh[(2*c2)*131 + p]; b = sKh[(2*c2+1)*131 + p]; okh[idx] = a | (b<<16);
        a = sKl[(2*c2)*131 + p]; b = sKl[(2*c2+1)*131 + p]; okl[idx] = a | (b<<16);
    }
}

// ---------------------------------------------------------------------------
// Kernel 3: HMMA flash attention, BK=64, key-split across 2 blocks, 2 CTAs/SM.
// Writes unnormalized partial ctx + partial denominators.
// Buffer (36864 B): Khi[64][72u16]@0, Klo@9216, Ghi[64c][72u16]@18432, Glo@27648
// ---------------------------------------------------------------------------
#define KLO_OFF 9216u
#define G_OFF   18432u
#define GLO_OFF 9216u
#define BUFSZ   36864u
#define ATTN_SMEM (3*36864)
#define ESHIFT  20.0f

__device__ __forceinline__ void load_kg(u32 buf, int n, int k0, int tid) {
    const u16* kh = g_kh + (size_t)(n*4096 + k0)*64;
    const u16* kl = g_kl + (size_t)(n*4096 + k0)*64;
    const u16* gh = g_gh + (size_t)n*CHW + k0;
    const u16* gl = g_gl + (size_t)n*CHW + k0;
    #pragma unroll
    for (int ii = 0; ii < 2; ii++) {
        int i = tid + ii*256;
        int row = i >> 3, seg = i & 7;       // row: key for K, channel for G
        u32 sk = buf + (u32)row*144u + (u32)seg*16u;
        cpasync16(sk,           kh + row*64 + seg*8);
        cpasync16(sk + KLO_OFF, kl + row*64 + seg*8);
        u32 sg = buf + G_OFF + (u32)row*144u + (u32)seg*16u;
        cpasync16(sg,           gh + (size_t)row*HW + seg*8);
        cpasync16(sg + GLO_OFF, gl + (size_t)row*HW + seg*8);
    }
}

__global__ __launch_bounds__(256, 2)
void attn_kernel() {
    extern __shared__ char smc[];
    u32 sb = smem_u32(smc);
    const int tid = threadIdx.x;
    const int w = tid >> 5, lane = tid & 31;
    const int qt = blockIdx.x, kh = blockIdx.y, n = blockIdx.z;
    const int q0 = qt * 128;
    const int kbase = kh * 2048;
    const int r0 = lane >> 2, cb = (lane & 3) * 2;

    // ---- Q fragments straight from gmem ----
    u32 qh[4][4], ql[4][4];
    {
        const u16* qbh = g_qh + (size_t)(n*4096 + q0 + w*16)*64;
        const u16* qbl = g_ql + (size_t)(n*4096 + q0 + w*16)*64;
        #pragma unroll
        for (int kc = 0; kc < 4; kc++)
            #pragma unroll
            for (int r = 0; r < 4; r++) {
                int off = (r0 + (r & 1)*8)*64 + cb + (r >> 1)*8 + kc*16;
                qh[kc][r] = *(const u32*)(qbh + off);
                ql[kc][r] = *(const u32*)(qbl + off);
            }
    }

    float ctx[8][4];
    #pragma unroll
    for (int t = 0; t < 8; t++)
        #pragma unroll
        for (int r = 0; r < 4; r++) ctx[t][r] = 0.f;
    float lA = 0.f, lB = 0.f;

    load_kg(sb, n, kbase, tid);
    CP_COMMIT();

    const u32 lm_row = (u32)(lane & 15);
    const u32 lm_hi  = (u32)(lane >> 4) * 16u;

    for (int kt = 0; kt < 32; kt++) {
        u32 cur = sb + (u32)(kt % 3) * BUFSZ;
        if (kt < 31) {
            load_kg(sb + (u32)((kt + 1) % 3) * BUFSZ, n, kbase + (kt + 1) * 64, tid);
            CP_COMMIT();
            CP_WAIT(1);
        } else {
            CP_WAIT(0);
        }
        __syncthreads();   // single barrier per tile

        // ---- S = Q·K^T (3 passes), 4 accumulator chains ----
        float sacc[8][4];
        #pragma unroll
        for (int t = 0; t < 8; t++)
            #pragma unroll
            for (int r = 0; r < 4; r++) sacc[t][r] = 0.f;

        #pragma unroll
        for (int ntp = 0; ntp < 2; ntp++) {
            u32 ra0 = cur + ((2*ntp)*16u   + lm_row)*144u + lm_hi;
            u32 ra1 = cur + ((2*ntp+1)*16u + lm_row)*144u + lm_hi;
            float* s0 = sacc[4*ntp];
            float* s1 = sacc[4*ntp+1];
            float* s2 = sacc[4*ntp+2];
            float* s3 = sacc[4*ntp+3];
            #pragma unroll
            for (int kc = 0; kc < 4; kc++) {
                u32 b0h[4], b0l[4], b1h[4], b1l[4];
                ldsm4(b0h, ra0 + kc*32u);
                ldsm4(b1h, ra1 + kc*32u);
                ldsm4(b0l, ra0 + KLO_OFF + kc*32u);
                ldsm4(b1l, ra1 + KLO_OFF + kc*32u);
                mma16816(s0, qh[kc], b0h[0], b0h[2]);
                mma16816(s1, qh[kc], b0h[1], b0h[3]);
                mma16816(s2, qh[kc], b1h[0], b1h[2]);
                mma16816(s3, qh[kc], b1h[1], b1h[3]);
                mma16816(s0, qh[kc], b0l[0], b0l[2]);
                mma16816(s1, qh[kc], b0l[1], b0l[3]);
                mma16816(s2, qh[kc], b1l[0], b1l[2]);
                mma16816(s3, qh[kc], b1l[1], b1l[3]);
                mma16816(s0, ql[kc], b0h[0], b0h[2]);
                mma16816(s1, ql[kc], b0h[1], b0h[3]);
                mma16816(s2, ql[kc], b1h[0], b1h[2]);
                mma16816(s3, ql[kc], b1h[1], b1h[3]);
            }
        }

        // ---- exp(s - SHIFT), denominator, pack to P frags ----
        u32 pfh[4][4], pfl[4][4];
        #pragma unroll
        for (int j = 0; j < 4; j++) {
            #pragma unroll
            for (int half = 0; half < 2; half++) {
                int t = 2*j + half;
                float p0 = __expf(sacc[t][0] - ESHIFT);
                float p1 = __expf(sacc[t][1] - ESHIFT);
                float p2 = __expf(sacc[t][2] - ESHIFT);
                float p3 = __expf(sacc[t][3] - ESHIFT);
                lA += p0 + p1; lB += p2 + p3;
                u32 h2, l2;
                split2(p0, p1, h2, l2);
                pfh[j][2*half]   = h2; pfl[j][2*half]   = l2;
                split2(p2, p3, h2, l2);
                pfh[j][2*half+1] = h2; pfl[j][2*half+1] = l2;
            }
        }

        // ---- ctx += P·G^T (3 passes), 4 chains ----
        #pragma unroll
        for (int cgp = 0; cgp < 2; cgp++) {
            u32 ra0 = cur + G_OFF + ((2*cgp)*16u   + lm_row)*144u + lm_hi;
            u32 ra1 = cur + G_OFF + ((2*cgp+1)*16u + lm_row)*144u + lm_hi;
            float* c0 = ctx[4*cgp];
            float* c1 = ctx[4*cgp+1];
            float* c2 = ctx[4*cgp+2];
            float* c3 = ctx[4*cgp+3];
            #pragma unroll
            for (int j = 0; j < 4; j++) {
                u32 b0h[4], b0l[4], b1h[4], b1l[4];
                ldsm4(b0h, ra0 + j*32u);
                ldsm4(b1h, ra1 + j*32u);
                ldsm4(b0l, ra0 + GLO_OFF + j*32u);
                ldsm4(b1l, ra1 + GLO_OFF + j*32u);
                mma16816(c0, pfh[j], b0h[0], b0h[2]);
                mma16816(c1, pfh[j], b0h[1], b0h[3]);
                mma16816(c2, pfh[j], b1h[0], b1h[2]);
                mma16816(c3, pfh[j], b1h[1], b1h[3]);
                mma16816(c0, pfh[j], b0l[0], b0l[2]);
                mma16816(c1, pfh[j], b0l[1], b0l[3]);
                mma16816(c2, pfh[j], b1l[0], b1l[2]);
                mma16816(c3, pfh[j], b1l[1], b1l[3]);
                mma16816(c0, pfl[j], b0h[0], b0h[2]);
                mma16816(c1, pfl[j], b0h[1], b0h[3]);
                mma16816(c2, pfl[j], b1h[0], b1h[2]);
                mma16816(c3, pfl[j], b1h[1], b1h[3]);
            }
        }
    }

    // ---- write partials (unnormalized) ----
    lA += __shfl_xor_sync(0xffffffffu, lA, 1);
    lA += __shfl_xor_sync(0xffffffffu, lA, 2);
    lB += __shfl_xor_sync(0xffffffffu, lB, 1);
    lB += __shfl_xor_sync(0xffffffffu, lB, 2);
    if ((lane & 3) == 0) {
        int db = (n*2 + kh)*4096 + q0 + w*16;
        g_pden[db + r0]     = lA;
        g_pden[db + r0 + 8] = lB;
    }
    size_t pb = (size_t)((n*2 + kh)*32 + qt) * 8192;   // [q 128][c 64]
    #pragma unroll
    for (int t = 0; t < 8; t++) {
        int c = t*8 + cb;
        #pragma unroll
        for (int rp = 0; rp < 2; rp++) {
            int q = w*16 + r0 + 8*rp;
            *reinterpret_cast<ull*>(&g_pctx[pb + (size_t)q*64 + c]) =
                pk2(ctx[t][2*rp], ctx[t][2*rp+1]);
        }
    }
}

// ---------------------------------------------------------------------------
// Kernel 4: combine halves, normalize, transpose, store
// ---------------------------------------------------------------------------
__global__ __launch_bounds__(256)
void combine_kernel(float* __restrict__ out) {
    __shared__ float inv[128];
    __shared__ float Os[64*133];
    int tid = threadIdx.x;
    int qt = blockIdx.x, n = blockIdx.y;
    int q0 = qt * 128;
    if (tid < 128) {
        float dA = g_pden[(n*2)*4096 + q0 + tid];
        float dB = g_pden[(n*2+1)*4096 + q0 + tid];
        inv[tid] = 1.0f / (dA + dB);
    }
    __syncthreads();
    size_t bA = (size_t)((n*2)*32 + qt) * 8192;
    size_t bB = (size_t)((n*2+1)*32 + qt) * 8192;
    for (int i = tid; i < 4096; i += 256) {
        int q = i >> 5, cp = i & 31;
        ull a = *reinterpret_cast<const ull*>(&g_pctx[bA + (size_t)q*64 + 2*cp]);
        ull b = *reinterpret_cast<const ull*>(&g_pctx[bB + (size_t)q*64 + 2*cp]);
        float ax, ay, bx, by;
        upk2(a, ax, ay); upk2(b, bx, by);
        float iv = inv[q];
        Os[(2*cp)*133 + q]   = (ax + bx) * iv;
        Os[(2*cp+1)*133 + q] = (ay + by) * iv;
    }
    __syncthreads();
    size_t nb = (size_t)n*CHW;
    for (int i = tid; i < 8192; i += 256) {
        int c = i >> 7, q = i & 127;
        out[nb + (size_t)c*HW + q0 + q] = Os[c*133 + q];
    }
}

// ---------------------------------------------------------------------------
extern "C" void kernel_launch(void* const* d_in, const int* in_sizes, int n_in,
                              void* d_out, int out_size) {
    const float* x     = (const float*)d_in[0];
    const float* h0    = (const float*)d_in[1];
    const float* h1    = (const float*)d_in[2];
    const float* Wq    = (const float*)d_in[3];
    const float* bq    = (const float*)d_in[4];
    const float* gq    = (const float*)d_in[5];
    const float* betaq = (const float*)d_in[6];
    const float* Wk    = (const float*)d_in[7];
    const float* bk    = (const float*)d_in[8];
    const float* gk    = (const float*)d_in[9];
    const float* betak = (const float*)d_in[10];
    const float* Wv    = (const float*)d_in[11];
    const float* bv    = (const float*)d_in[12];
    float* out = (float*)d_out;

    const int proj_smem = 14336 * 4;
    const int prep_smem = 33536 * 2 + 64;
    cudaFuncSetAttribute(proj_kernel, cudaFuncAttributeMaxDynamicSharedMemorySize, proj_smem);
    cudaFuncSetAttribute(prep_kernel, cudaFuncAttributeMaxDynamicSharedMemorySize, prep_smem);
    cudaFuncSetAttribute(attn_kernel, cudaFuncAttributeMaxDynamicSharedMemorySize, ATTN_SMEM);

    proj_kernel<<<512, 256, proj_smem>>>(x, h0, h1, Wq, bq, Wk, bk, Wv, bv);
    stats_kernel<<<128, 256>>>(gq, betaq, gk, betak);
    prep_kernel<<<dim3(32, NB), 256, prep_smem>>>();
    attn_kernel<<<dim3(32, 2, NB), 256, ATTN_SMEM>>>();
    combine_kernel<<<dim3(32, NB), 256>>>(out);
}

// round 10
// speedup vs baseline: 1.0648x; 1.0648x over previous
#include <cuda_runtime.h>
#include <math.h>
#include <cstdint>

#define CH    64
#define HW    4096
#define NB    4
#define CHW   (CH*HW)
#define TOTAL (NB*CHW)

typedef unsigned long long ull;
typedef unsigned int       u32;
typedef unsigned short     u16;

// ------------------------- device scratch ----------------------------------
__device__ __align__(16) float g_yq[TOTAL];   // [n][c][p]
__device__ __align__(16) float g_yk[TOTAL];
__device__ float               g_aff[4*CH];
__device__ __align__(16) u16   g_gh[TOTAL];   // gated value hi/lo bf16 [n][c][p]
__device__ __align__(16) u16   g_gl[TOTAL];
__device__ __align__(16) u16   g_qh[TOTAL];   // Q' hi/lo bf16 [n][p][c]
__device__ __align__(16) u16   g_ql[TOTAL];
__device__ __align__(16) u16   g_kh[TOTAL];   // K' hi/lo bf16 [n][p][c]
__device__ __align__(16) u16   g_kl[TOTAL];

// ------------------------------ helpers ------------------------------------
__device__ __forceinline__ ull pk2(float x, float y) {
    ull r; asm("mov.b64 %0,{%1,%2};" : "=l"(r) : "f"(x), "f"(y)); return r;
}
__device__ __forceinline__ void upk2(ull v, float& x, float& y) {
    asm("mov.b64 {%0,%1},%2;" : "=f"(x), "=f"(y) : "l"(v));
}
__device__ __forceinline__ void fma2(ull& d, ull a, ull b) {
    asm("fma.rn.f32x2 %0,%1,%2,%0;" : "+l"(d) : "l"(a), "l"(b));
}
__device__ __forceinline__ ull add2_(ull a, ull b) {
    ull r; asm("add.rn.f32x2 %0,%1,%2;" : "=l"(r) : "l"(a), "l"(b)); return r;
}
__device__ __forceinline__ ull mul2_(ull a, ull b) {
    ull r; asm("mul.rn.f32x2 %0,%1,%2;" : "=l"(r) : "l"(a), "l"(b)); return r;
}
__device__ __forceinline__ ull ld2(const float* p) { return *reinterpret_cast<const ull*>(p); }

// split fp32 pair (a,b) -> bf16x2 hi + bf16x2 lo (low 16 bits = a)
__device__ __forceinline__ void split2(float a, float b, u32& h2, u32& l2) {
    asm("cvt.rn.bf16x2.f32 %0, %1, %2;" : "=r"(h2) : "f"(b), "f"(a));
    float fa = __uint_as_float(h2 << 16);
    float fb = __uint_as_float(h2 & 0xffff0000u);
    asm("cvt.rn.bf16x2.f32 %0, %1, %2;" : "=r"(l2) : "f"(b - fb), "f"(a - fa));
}
__device__ __forceinline__ u32 smem_u32(const void* p) {
    u32 a; asm("{ .reg .u64 t; cvta.to.shared.u64 t, %1; cvt.u32.u64 %0, t; }" : "=r"(a) : "l"(p));
    return a;
}
__device__ __forceinline__ void cpasync16(u32 s, const void* g) {
    asm volatile("cp.async.cg.shared.global [%0], [%1], 16;" :: "r"(s), "l"(g) : "memory");
}
#define CP_COMMIT() asm volatile("cp.async.commit_group;" ::: "memory")
#define CP_WAIT(n)  asm volatile("cp.async.wait_group %0;" :: "n"(n) : "memory")

__device__ __forceinline__ void ldsm4(u32* t, u32 addr) {
    asm volatile("ldmatrix.sync.aligned.m8n8.x4.shared.b16 {%0,%1,%2,%3}, [%4];"
        : "=r"(t[0]), "=r"(t[1]), "=r"(t[2]), "=r"(t[3]) : "r"(addr));
}
__device__ __forceinline__ void mma16816(float* d, const u32* a, u32 b0, u32 b1) {
    asm volatile("mma.sync.aligned.m16n8k16.row.col.f32.bf16.bf16.f32 "
        "{%0,%1,%2,%3}, {%4,%5,%6,%7}, {%8,%9}, {%0,%1,%2,%3};"
        : "+f"(d[0]), "+f"(d[1]), "+f"(d[2]), "+f"(d[3])
        : "r"(a[0]), "r"(a[1]), "r"(a[2]), "r"(a[3]), "r"(b0), "r"(b1));
}

// ---------------------------------------------------------------------------
// Kernel 1: projections + gated value bf16 split. grid 512, 32 positions/blk
// ---------------------------------------------------------------------------
__global__ __launch_bounds__(256)
void proj_kernel(const float* __restrict__ x,
                 const float* __restrict__ h0,
                 const float* __restrict__ h1,
                 const float* __restrict__ Wq, const float* __restrict__ bq,
                 const float* __restrict__ Wk, const float* __restrict__ bk,
                 const float* __restrict__ Wv, const float* __restrict__ bv) {
    extern __shared__ float sm[];
    float* sWq = sm;
    float* sWk = sm + 4096;
    float* sWv = sm + 8192;
    float* xs  = sm + 12288;   // [64][32]

    int tid = threadIdx.x;
    for (int i = tid; i < 4096; i += 256) {
        sWq[i] = Wq[i]; sWk[i] = Wk[i]; sWv[i] = Wv[i];
    }
    int P0 = blockIdx.x * 32;
    int n  = P0 >> 12;
    int p0 = P0 & (HW - 1);
    const float* xb = x + (size_t)n*CHW + p0;
    for (int i = tid; i < 2048; i += 256) {
        int c = i >> 5, pp = i & 31;
        xs[c*32 + pp] = xb[(size_t)c*HW + pp];
    }
    __syncthreads();

    int ty = tid >> 4, tx = tid & 15;
    ull aq2[4], ak2[4], av2[4];
    #pragma unroll
    for (int io = 0; io < 4; io++) {
        int o = ty + 16*io;
        aq2[io] = pk2(bq[o], bq[o]);
        ak2[io] = pk2(bk[o], bk[o]);
        av2[io] = pk2(bv[o], bv[o]);
    }
    #pragma unroll 4
    for (int c = 0; c < 64; c++) {
        ull xv = ld2(&xs[c*32 + 2*tx]);
        #pragma unroll
        for (int io = 0; io < 4; io++) {
            int o = ty + 16*io;
            float wqs = sWq[o*64+c], wks = sWk[o*64+c], wvs = sWv[o*64+c];
            fma2(aq2[io], pk2(wqs,wqs), xv);
            fma2(ak2[io], pk2(wks,wks), xv);
            fma2(av2[io], pk2(wvs,wvs), xv);
        }
    }
    size_t base = (size_t)n*CHW + p0;
    #pragma unroll
    for (int io = 0; io < 4; io++) {
        int o = ty + 16*io;
        size_t idx = base + (size_t)o*HW + 2*tx;
        *reinterpret_cast<ull*>(&g_yq[idx]) = aq2[io];
        *reinterpret_cast<ull*>(&g_yk[idx]) = ak2[io];
        ull h0p = *reinterpret_cast<const ull*>(&h0[idx]);
        ull h1p = *reinterpret_cast<const ull*>(&h1[idx]);
        ull gv  = mul2_(add2_(h0p, h1p), av2[io]);
        float ga, gb; upk2(gv, ga, gb);
        u32 h2, l2; split2(ga, gb, h2, l2);
        *reinterpret_cast<u32*>(&g_gh[idx]) = h2;
        *reinterpret_cast<u32*>(&g_gl[idx]) = l2;
    }
}

// ---------------------------------------------------------------------------
// Kernel 2: BN stats -> affine coefs
// ---------------------------------------------------------------------------
__global__ __launch_bounds__(256)
void stats_kernel(const float* __restrict__ gq, const float* __restrict__ betaq,
                  const float* __restrict__ gk, const float* __restrict__ betak) {
    int ch    = blockIdx.x & 63;
    int which = blockIdx.x >> 6;
    const float* y = which ? g_yk : g_yq;
    int tid = threadIdx.x;
    float s = 0.f, sq = 0.f;
    for (int n = 0; n < NB; n++) {
        const float4* row = (const float4*)(y + (size_t)n*CHW + (size_t)ch*HW);
        for (int p = tid; p < 1024; p += 256) {
            float4 v = row[p];
            s  += (v.x + v.y) + (v.z + v.w);
            sq += (v.x*v.x + v.y*v.y) + (v.z*v.z + v.w*v.w);
        }
    }
    __shared__ float rs[256], rq[256];
    rs[tid] = s; rq[tid] = sq;
    __syncthreads();
    for (int st = 128; st > 0; st >>= 1) {
        if (tid < st) { rs[tid] += rs[tid+st]; rq[tid] += rq[tid+st]; }
        __syncthreads();
    }
    if (tid == 0) {
        const float invn = 1.0f / (NB * HW);
        float mean = rs[0] * invn;
        float var  = rq[0] * invn - mean*mean;
        float g = which ? gk[ch]    : gq[ch];
        float b = which ? betak[ch] : betaq[ch];
        float a = g * rsqrtf(var + 1e-5f);
        g_aff[which*128 + ch]      = a;
        g_aff[which*128 + 64 + ch] = b - mean*a;
    }
}

// ---------------------------------------------------------------------------
// Kernel 2.5: BN affine + relu, bf16 split, transpose [n][c][p] -> [n][p][c]
// ---------------------------------------------------------------------------
__global__ __launch_bounds__(256)
void prep_kernel() {
    extern __shared__ u16 sp[];
    u16* sQh = sp;
    u16* sQl = sp + 8384;
    u16* sKh = sp + 16768;
    u16* sKl = sp + 25152;
    int tid = threadIdx.x;
    int n = blockIdx.y, p0 = blockIdx.x * 128;
    size_t nb = (size_t)n*CHW;

    for (int i = tid; i < 2048; i += 256) {
        int c = i >> 5, j = i & 31;
        float4 vq = *(const float4*)&g_yq[nb + (size_t)c*HW + p0 + 4*j];
        float4 vk = *(const float4*)&g_yk[nb + (size_t)c*HW + p0 + 4*j];
        float aq = g_aff[c], bqv = g_aff[64+c];
        float ak = g_aff[128+c], bkv = g_aff[192+c];
        float q0f = fmaxf(0.f, aq*vq.x + bqv), q1f = fmaxf(0.f, aq*vq.y + bqv);
        float q2f = fmaxf(0.f, aq*vq.z + bqv), q3f = fmaxf(0.f, aq*vq.w + bqv);
        float k0f = fmaxf(0.f, ak*vk.x + bkv), k1f = fmaxf(0.f, ak*vk.y + bkv);
        float k2f = fmaxf(0.f, ak*vk.z + bkv), k3f = fmaxf(0.f, ak*vk.w + bkv);
        int base = c*131 + 4*j;
        u32 h2, l2;
        split2(q0f, q1f, h2, l2);
        sQh[base]   = (u16)h2; sQh[base+1] = (u16)(h2>>16);
        sQl[base]   = (u16)l2; sQl[base+1] = (u16)(l2>>16);
        split2(q2f, q3f, h2, l2);
        sQh[base+2] = (u16)h2; sQh[base+3] = (u16)(h2>>16);
        sQl[base+2] = (u16)l2; sQl[base+3] = (u16)(l2>>16);
        split2(k0f, k1f, h2, l2);
        sKh[base]   = (u16)h2; sKh[base+1] = (u16)(h2>>16);
        sKl[base]   = (u16)l2; sKl[base+1] = (u16)(l2>>16);
        split2(k2f, k3f, h2, l2);
        sKh[base+2] = (u16)h2; sKh[base+3] = (u16)(h2>>16);
        sKl[base+2] = (u16)l2; sKl[base+3] = (u16)(l2>>16);
    }
    __syncthreads();

    u32* oqh = (u32*)g_qh; u32* oql = (u32*)g_ql;
    u32* okh = (u32*)g_kh; u32* okl = (u32*)g_kl;
    for (int i = tid; i < 4096; i += 256) {
        int p = i >> 5, c2 = i & 31;
        u32 idx = (u32)(n*4096 + p0 + p)*32 + c2;
        u32 a, b;
        a = sQh[(2*c2)*131 + p]; b = sQh[(2*c2+1)*131 + p]; oqh[idx] = a | (b<<16);
        a = sQl[(2*c2)*131 + p]; b = sQl[(2*c2+1)*131 + p]; oql[idx] = a | (b<<16);
        a = sKh[(2*c2)*131 + p]; b = sKh[(2*c2+1)*131 + p]; okh[idx] = a | (b<<16);
        a = sKl[(2*c2)*131 + p]; b = sKl[(2*c2+1)*131 + p]; okl[idx] = a | (b<<16);
    }
}

// ---------------------------------------------------------------------------
// Kernel 3: HMMA flash attention, BK=64, 4 smem buffers, cross-tile software
// pipelining: ctx-MMA(t-1) interleaved with exp-epilogue(t) inside each warp.
// Buffer (36864 B): Khi[64][72u16]@0, Klo@9216, Ghi[64c][72u16]@18432, Glo@27648
// ---------------------------------------------------------------------------
#define KLO_OFF 9216u
#define G_OFF   18432u
#define GLO_OFF 9216u
#define BUFSZ   36864u
#define ATTN_SMEM (4*36864)
#define ESHIFT  20.0f

__device__ __forceinline__ void load_kg(u32 buf, int n, int k0, int tid) {
    const u16* kh = g_kh + (size_t)(n*4096 + k0)*64;
    const u16* kl = g_kl + (size_t)(n*4096 + k0)*64;
    const u16* gh = g_gh + (size_t)n*CHW + k0;
    const u16* gl = g_gl + (size_t)n*CHW + k0;
    #pragma unroll
    for (int ii = 0; ii < 2; ii++) {
        int i = tid + ii*256;
        int row = i >> 3, seg = i & 7;
        u32 sk = buf + (u32)row*144u + (u32)seg*16u;
        cpasync16(sk,           kh + row*64 + seg*8);
        cpasync16(sk + KLO_OFF, kl + row*64 + seg*8);
        u32 sg = buf + G_OFF + (u32)row*144u + (u32)seg*16u;
        cpasync16(sg,           gh + (size_t)row*HW + seg*8);
        cpasync16(sg + GLO_OFF, gl + (size_t)row*HW + seg*8);
    }
}

__global__ __launch_bounds__(256, 1)
void attn_kernel(float* __restrict__ out) {
    extern __shared__ char smc[];
    u32 sb = smem_u32(smc);
    const int tid = threadIdx.x;
    const int w = tid >> 5, lane = tid & 31;
    const int n = blockIdx.y, q0 = blockIdx.x * 128;
    const size_t nb = (size_t)n * CHW;
    const int r0 = lane >> 2, cb = (lane & 3) * 2;

    // ---- Q fragments straight from gmem ----
    u32 qh[4][4], ql[4][4];
    {
        const u16* qbh = g_qh + (size_t)(n*4096 + q0 + w*16)*64;
        const u16* qbl = g_ql + (size_t)(n*4096 + q0 + w*16)*64;
        #pragma unroll
        for (int kc = 0; kc < 4; kc++)
            #pragma unroll
            for (int r = 0; r < 4; r++) {
                int off = (r0 + (r & 1)*8)*64 + cb + (r >> 1)*8 + kc*16;
                qh[kc][r] = *(const u32*)(qbh + off);
                ql[kc][r] = *(const u32*)(qbl + off);
            }
    }

    float ctx[8][4];
    #pragma unroll
    for (int t = 0; t < 8; t++)
        #pragma unroll
        for (int r = 0; r < 4; r++) ctx[t][r] = 0.f;
    float lA = 0.f, lB = 0.f;
    float sacc[8][4];
    u32 pfh0[4][4], pfl0[4][4], pfh1[4][4], pfl1[4][4];

    const u32 lm_row = (u32)(lane & 15);
    const u32 lm_hi  = (u32)(lane >> 4) * 16u;

    // ---- S = Q·K^T for one tile (3 passes, 4 chains) ----
    auto do_smma = [&](u32 cur) {
        #pragma unroll
        for (int t = 0; t < 8; t++)
            #pragma unroll
            for (int r = 0; r < 4; r++) sacc[t][r] = 0.f;
        #pragma unroll
        for (int ntp = 0; ntp < 2; ntp++) {
            u32 ra0 = cur + ((2*ntp)*16u   + lm_row)*144u + lm_hi;
            u32 ra1 = cur + ((2*ntp+1)*16u + lm_row)*144u + lm_hi;
            float* s0 = sacc[4*ntp];
            float* s1 = sacc[4*ntp+1];
            float* s2 = sacc[4*ntp+2];
            float* s3 = sacc[4*ntp+3];
            #pragma unroll
            for (int kc = 0; kc < 4; kc++) {
                u32 b0h[4], b0l[4], b1h[4], b1l[4];
                ldsm4(b0h, ra0 + kc*32u);
                ldsm4(b1h, ra1 + kc*32u);
                ldsm4(b0l, ra0 + KLO_OFF + kc*32u);
                ldsm4(b1l, ra1 + KLO_OFF + kc*32u);
                mma16816(s0, qh[kc], b0h[0], b0h[2]);
                mma16816(s1, qh[kc], b0h[1], b0h[3]);
                mma16816(s2, qh[kc], b1h[0], b1h[2]);
                mma16816(s3, qh[kc], b1h[1], b1h[3]);
                mma16816(s0, qh[kc], b0l[0], b0l[2]);
                mma16816(s1, qh[kc], b0l[1], b0l[3]);
                mma16816(s2, qh[kc], b1l[0], b1l[2]);
                mma16816(s3, qh[kc], b1l[1], b1l[3]);
                mma16816(s0, ql[kc], b0h[0], b0h[2]);
                mma16816(s1, ql[kc], b0h[1], b0h[3]);
                mma16816(s2, ql[kc], b1h[0], b1h[2]);
                mma16816(s3, ql[kc], b1h[1], b1h[3]);
            }
        }
    };

    // ---- epilogue piece: chunk = 0..7, consumes sacc[chunk] -> P set ----
    auto epi_piece = [&](int chunk, u32 (&phC)[4][4], u32 (&plC)[4][4]) {
        float p0 = __expf(sacc[chunk][0] - ESHIFT);
        float p1 = __expf(sacc[chunk][1] - ESHIFT);
        float p2 = __expf(sacc[chunk][2] - ESHIFT);
        float p3 = __expf(sacc[chunk][3] - ESHIFT);
        lA += p0 + p1; lB += p2 + p3;
        int j2 = chunk >> 1, half = chunk & 1;
        u32 h2, l2;
        split2(p0, p1, h2, l2);
        phC[j2][2*half]   = h2; plC[j2][2*half]   = l2;
        split2(p2, p3, h2, l2);
        phC[j2][2*half+1] = h2; plC[j2][2*half+1] = l2;
    };

    // ---- ctx(prev) interleaved with epilogue(cur) ----
    auto do_ctx_epi = [&](u32 gslot, u32 (&phP)[4][4], u32 (&plP)[4][4],
                          u32 (&phC)[4][4], u32 (&plC)[4][4]) {
        #pragma unroll
        for (int cgp = 0; cgp < 2; cgp++) {
            u32 ra0 = gslot + G_OFF + ((2*cgp)*16u   + lm_row)*144u + lm_hi;
            u32 ra1 = gslot + G_OFF + ((2*cgp+1)*16u + lm_row)*144u + lm_hi;
            float* c0 = ctx[4*cgp];
            float* c1 = ctx[4*cgp+1];
            float* c2 = ctx[4*cgp+2];
            float* c3 = ctx[4*cgp+3];
            #pragma unroll
            for (int j = 0; j < 4; j++) {
                u32 b0h[4], b0l[4], b1h[4], b1l[4];
                ldsm4(b0h, ra0 + j*32u);
                ldsm4(b1h, ra1 + j*32u);
                ldsm4(b0l, ra0 + GLO_OFF + j*32u);
                ldsm4(b1l, ra1 + GLO_OFF + j*32u);
                mma16816(c0, phP[j], b0h[0], b0h[2]);
                mma16816(c1, phP[j], b0h[1], b0h[3]);
                mma16816(c2, phP[j], b1h[0], b1h[2]);
                mma16816(c3, phP[j], b1h[1], b1h[3]);
                mma16816(c0, phP[j], b0l[0], b0l[2]);
                mma16816(c1, phP[j], b0l[1], b0l[3]);
                mma16816(c2, phP[j], b1l[0], b1l[2]);
                mma16816(c3, phP[j], b1l[1], b1l[3]);
                mma16816(c0, plP[j], b0h[0], b0h[2]);
                mma16816(c1, plP[j], b0h[1], b0h[3]);
                mma16816(c2, plP[j], b1h[0], b1h[2]);
                mma16816(c3, plP[j], b1h[1], b1h[3]);
                epi_piece(cgp*4 + j, phC, plC);   // overlap MUFU with HMMA
            }
        }
    };

    // ---- ctx only (drain) ----
    auto do_ctx = [&](u32 gslot, u32 (&phP)[4][4], u32 (&plP)[4][4]) {
        #pragma unroll
        for (int cgp = 0; cgp < 2; cgp++) {
            u32 ra0 = gslot + G_OFF + ((2*cgp)*16u   + lm_row)*144u + lm_hi;
            u32 ra1 = gslot + G_OFF + ((2*cgp+1)*16u + lm_row)*144u + lm_hi;
            float* c0 = ctx[4*cgp];
            float* c1 = ctx[4*cgp+1];
            float* c2 = ctx[4*cgp+2];
            float* c3 = ctx[4*cgp+3];
            #pragma unroll
            for (int j = 0; j < 4; j++) {
                u32 b0h[4], b0l[4], b1h[4], b1l[4];
                ldsm4(b0h, ra0 + j*32u);
                ldsm4(b1h, ra1 + j*32u);
                ldsm4(b0l, ra0 + GLO_OFF + j*32u);
                ldsm4(b1l, ra1 + GLO_OFF + j*32u);
                mma16816(c0, phP[j], b0h[0], b0h[2]);
                mma16816(c1, phP[j], b0h[1], b0h[3]);
                mma16816(c2, phP[j], b1h[0], b1h[2]);
                mma16816(c3, phP[j], b1h[1], b1h[3]);
                mma16816(c0, phP[j], b0l[0], b0l[2]);
                mma16816(c1, phP[j], b0l[1], b0l[3]);
                mma16816(c2, phP[j], b1l[0], b1l[2]);
                mma16816(c3, phP[j], b1l[1], b1l[3]);
                mma16816(c0, plP[j], b0h[0], b0h[2]);
                mma16816(c1, plP[j], b0h[1], b0h[3]);
                mma16816(c2, plP[j], b1h[0], b1h[2]);
                mma16816(c3, plP[j], b1h[1], b1h[3]);
            }
        }
    };

    // prologue: load tiles 0,1; S(0); epilogue(0) -> set0
    load_kg(sb,          n, 0,  tid); CP_COMMIT();
    load_kg(sb + BUFSZ,  n, 64, tid); CP_COMMIT();
    CP_WAIT(1);
    __syncthreads();
    do_smma(sb);
    #pragma unroll
    for (int chunk = 0; chunk < 8; chunk++) epi_piece(chunk, pfh0, pfl0);

    // pipelined body: iter t issues load(t+1), S(t), ctx(t-1)+epi(t)
    auto body = [&](int t, u32 (&phP)[4][4], u32 (&plP)[4][4],
                    u32 (&phC)[4][4], u32 (&plC)[4][4]) {
        if (t < 63) {
            load_kg(sb + (u32)((t + 1) & 3) * BUFSZ, n, (t + 1) * 64, tid);
            CP_COMMIT();
            CP_WAIT(1);
        } else {
            CP_WAIT(0);
        }
        __syncthreads();
        do_smma(sb + (u32)(t & 3) * BUFSZ);
        do_ctx_epi(sb + (u32)((t - 1) & 3) * BUFSZ, phP, plP, phC, plC);
    };

    for (int t = 1; t + 1 < 64; t += 2) {
        body(t,     pfh0, pfl0, pfh1, pfl1);
        body(t + 1, pfh1, pfl1, pfh0, pfl0);
    }
    body(63, pfh0, pfl0, pfh1, pfl1);
    do_ctx(sb + 3u * BUFSZ, pfh1, pfl1);   // drain ctx(63), G slot 63&3=3

    // ---- finalize ----
    lA += __shfl_xor_sync(0xffffffffu, lA, 1);
    lA += __shfl_xor_sync(0xffffffffu, lA, 2);
    lB += __shfl_xor_sync(0xffffffffu, lB, 1);
    lB += __shfl_xor_sync(0xffffffffu, lB, 2);
    float invA = 1.0f / lA, invB = 1.0f / lB;

    // Os (33.8 KB at base) overlaps slot0 only; laggard warps read slots 2/3.
    float* Os = (float*)smc;   // [64][132]
    #pragma unroll
    for (int t = 0; t < 8; t++) {
        #pragma unroll
        for (int r = 0; r < 4; r++) {
            int row = r0 + 8*(r >> 1);
            int c   = t*8 + cb + (r & 1);
            Os[c*132 + w*16 + row] = ctx[t][r] * ((r >> 1) ? invB : invA);
        }
    }
    __syncthreads();
    for (int i = tid; i < 8192; i += 256) {
        int c = i >> 7, q = i & 127;
        out[nb + (size_t)c*HW + q0 + q] = Os[c*132 + q];
    }
}

// ---------------------------------------------------------------------------
extern "C" void kernel_launch(void* const* d_in, const int* in_sizes, int n_in,
                              void* d_out, int out_size) {
    const float* x     = (const float*)d_in[0];
    const float* h0    = (const float*)d_in[1];
    const float* h1    = (const float*)d_in[2];
    const float* Wq    = (const float*)d_in[3];
    const float* bq    = (const float*)d_in[4];
    const float* gq    = (const float*)d_in[5];
    const float* betaq = (const float*)d_in[6];
    const float* Wk    = (const float*)d_in[7];
    const float* bk    = (const float*)d_in[8];
    const float* gk    = (const float*)d_in[9];
    const float* betak = (const float*)d_in[10];
    const float* Wv    = (const float*)d_in[11];
    const float* bv    = (const float*)d_in[12];
    float* out = (float*)d_out;

    const int proj_smem = 14336 * 4;
    const int prep_smem = 33536 * 2 + 64;
    cudaFuncSetAttribute(proj_kernel, cudaFuncAttributeMaxDynamicSharedMemorySize, proj_smem);
    cudaFuncSetAttribute(prep_kernel, cudaFuncAttributeMaxDynamicSharedMemorySize, prep_smem);
    cudaFuncSetAttribute(attn_kernel, cudaFuncAttributeMaxDynamicSharedMemorySize, ATTN_SMEM);

    proj_kernel<<<512, 256, proj_smem>>>(x, h0, h1, Wq, bq, Wk, bk, Wv, bv);
    stats_kernel<<<128, 256>>>(gq, betaq, gk, betak);
    prep_kernel<<<dim3(32, NB), 256, prep_smem>>>();
    attn_kernel<<<dim3(32, NB), 256, ATTN_SMEM>>>(out);
}

// round 12
// speedup vs baseline: 1.2320x; 1.1570x over previous
#include <cuda_runtime.h>
#include <cuda_fp16.h>
#include <math.h>
#include <cstdint>

#define CH    64
#define HW    4096
#define NB    4
#define CHW   (CH*HW)
#define TOTAL (NB*CHW)

typedef unsigned long long ull;
typedef unsigned int       u32;
typedef unsigned short     u16;

// ------------------------- device scratch ----------------------------------
__device__ __align__(16) float g_yq[TOTAL];   // [n][c][p]
__device__ __align__(16) float g_yk[TOTAL];
__device__ float               g_aff[4*CH];
__device__ __align__(16) u16   g_gh[TOTAL];   // gated value hi/lo bf16 [n][c][p]
__device__ __align__(16) u16   g_gl[TOTAL];
__device__ __align__(16) u16   g_q16h[TOTAL]; // Q' fp16 hi [n][p][c]
__device__ __align__(16) u16   g_q16l[TOTAL]; // Q' fp16 lo
__device__ __align__(16) u16   g_k16[TOTAL];  // K' fp16 [n][p][c]

// ------------------------------ helpers ------------------------------------
__device__ __forceinline__ ull pk2(float x, float y) {
    ull r; asm("mov.b64 %0,{%1,%2};" : "=l"(r) : "f"(x), "f"(y)); return r;
}
__device__ __forceinline__ void upk2(ull v, float& x, float& y) {
    asm("mov.b64 {%0,%1},%2;" : "=f"(x), "=f"(y) : "l"(v));
}
__device__ __forceinline__ void fma2(ull& d, ull a, ull b) {
    asm("fma.rn.f32x2 %0,%1,%2,%0;" : "+l"(d) : "l"(a), "l"(b));
}
__device__ __forceinline__ ull add2_(ull a, ull b) {
    ull r; asm("add.rn.f32x2 %0,%1,%2;" : "=l"(r) : "l"(a), "l"(b)); return r;
}
__device__ __forceinline__ ull mul2_(ull a, ull b) {
    ull r; asm("mul.rn.f32x2 %0,%1,%2;" : "=l"(r) : "l"(a), "l"(b)); return r;
}
__device__ __forceinline__ ull ld2(const float* p) { return *reinterpret_cast<const ull*>(p); }

// split fp32 pair (a,b) -> bf16x2 hi + bf16x2 lo (low 16 bits = a)
__device__ __forceinline__ void split2(float a, float b, u32& h2, u32& l2) {
    asm("cvt.rn.bf16x2.f32 %0, %1, %2;" : "=r"(h2) : "f"(b), "f"(a));
    float fa = __uint_as_float(h2 << 16);
    float fb = __uint_as_float(h2 & 0xffff0000u);
    asm("cvt.rn.bf16x2.f32 %0, %1, %2;" : "=r"(l2) : "f"(b - fb), "f"(a - fa));
}
// split fp32 pair (a,b) -> fp16x2 hi + fp16x2 lo
__device__ __forceinline__ void split2h(float a, float b, u32& h2, u32& l2) {
    __half2 h = __floats2half2_rn(a, b);
    float2 f = __half22float2(h);
    __half2 l = __floats2half2_rn(a - f.x, b - f.y);
    h2 = *reinterpret_cast<u32*>(&h);
    l2 = *reinterpret_cast<u32*>(&l);
}
__device__ __forceinline__ u32 pack2h(float a, float b) {
    __half2 h = __floats2half2_rn(a, b);
    return *reinterpret_cast<u32*>(&h);
}
__device__ __forceinline__ u32 smem_u32(const void* p) {
    u32 a; asm("{ .reg .u64 t; cvta.to.shared.u64 t, %1; cvt.u32.u64 %0, t; }" : "=r"(a) : "l"(p));
    return a;
}
__device__ __forceinline__ void cpasync16(u32 s, const void* g) {
    asm volatile("cp.async.cg.shared.global [%0], [%1], 16;" :: "r"(s), "l"(g) : "memory");
}
#define CP_COMMIT() asm volatile("cp.async.commit_group;" ::: "memory")
#define CP_WAIT(n)  asm volatile("cp.async.wait_group %0;" :: "n"(n) : "memory")

__device__ __forceinline__ void ldsm4(u32* t, u32 addr) {
    asm volatile("ldmatrix.sync.aligned.m8n8.x4.shared.b16 {%0,%1,%2,%3}, [%4];"
        : "=r"(t[0]), "=r"(t[1]), "=r"(t[2]), "=r"(t[3]) : "r"(addr));
}
// D += A * B   bf16
__device__ __forceinline__ void mma16816(float* d, const u32* a, u32 b0, u32 b1) {
    asm volatile("mma.sync.aligned.m16n8k16.row.col.f32.bf16.bf16.f32 "
        "{%0,%1,%2,%3}, {%4,%5,%6,%7}, {%8,%9}, {%0,%1,%2,%3};"
        : "+f"(d[0]), "+f"(d[1]), "+f"(d[2]), "+f"(d[3])
        : "r"(a[0]), "r"(a[1]), "r"(a[2]), "r"(a[3]), "r"(b0), "r"(b1));
}
// D += A * B   fp16
__device__ __forceinline__ void mma16816h(float* d, const u32* a, u32 b0, u32 b1) {
    asm volatile("mma.sync.aligned.m16n8k16.row.col.f32.f16.f16.f32 "
        "{%0,%1,%2,%3}, {%4,%5,%6,%7}, {%8,%9}, {%0,%1,%2,%3};"
        : "+f"(d[0]), "+f"(d[1]), "+f"(d[2]), "+f"(d[3])
        : "r"(a[0]), "r"(a[1]), "r"(a[2]), "r"(a[3]), "r"(b0), "r"(b1));
}

// ---------------------------------------------------------------------------
// Kernel 1: projections + gated value bf16 split. grid 512, 32 positions/blk
// ---------------------------------------------------------------------------
__global__ __launch_bounds__(256)
void proj_kernel(const float* __restrict__ x,
                 const float* __restrict__ h0,
                 const float* __restrict__ h1,
                 const float* __restrict__ Wq, const float* __restrict__ bq,
                 const float* __restrict__ Wk, const float* __restrict__ bk,
                 const float* __restrict__ Wv, const float* __restrict__ bv) {
    extern __shared__ float sm[];
    float* sWq = sm;
    float* sWk = sm + 4096;
    float* sWv = sm + 8192;
    float* xs  = sm + 12288;   // [64][32]

    int tid = threadIdx.x;
    for (int i = tid; i < 4096; i += 256) {
        sWq[i] = Wq[i]; sWk[i] = Wk[i]; sWv[i] = Wv[i];
    }
    int P0 = blockIdx.x * 32;
    int n  = P0 >> 12;
    int p0 = P0 & (HW - 1);
    const float* xb = x + (size_t)n*CHW + p0;
    for (int i = tid; i < 2048; i += 256) {
        int c = i >> 5, pp = i & 31;
        xs[c*32 + pp] = xb[(size_t)c*HW + pp];
    }
    __syncthreads();

    int ty = tid >> 4, tx = tid & 15;
    ull aq2[4], ak2[4], av2[4];
    #pragma unroll
    for (int io = 0; io < 4; io++) {
        int o = ty + 16*io;
        aq2[io] = pk2(bq[o], bq[o]);
        ak2[io] = pk2(bk[o], bk[o]);
        av2[io] = pk2(bv[o], bv[o]);
    }
    #pragma unroll 4
    for (int c = 0; c < 64; c++) {
        ull xv = ld2(&xs[c*32 + 2*tx]);
        #pragma unroll
        for (int io = 0; io < 4; io++) {
            int o = ty + 16*io;
            float wqs = sWq[o*64+c], wks = sWk[o*64+c], wvs = sWv[o*64+c];
            fma2(aq2[io], pk2(wqs,wqs), xv);
            fma2(ak2[io], pk2(wks,wks), xv);
            fma2(av2[io], pk2(wvs,wvs), xv);
        }
    }
    size_t base = (size_t)n*CHW + p0;
    #pragma unroll
    for (int io = 0; io < 4; io++) {
        int o = ty + 16*io;
        size_t idx = base + (size_t)o*HW + 2*tx;
        *reinterpret_cast<ull*>(&g_yq[idx]) = aq2[io];
        *reinterpret_cast<ull*>(&g_yk[idx]) = ak2[io];
        ull h0p = *reinterpret_cast<const ull*>(&h0[idx]);
        ull h1p = *reinterpret_cast<const ull*>(&h1[idx]);
        ull gv  = mul2_(add2_(h0p, h1p), av2[io]);
        float ga, gb; upk2(gv, ga, gb);
        u32 h2, l2; split2(ga, gb, h2, l2);
        *reinterpret_cast<u32*>(&g_gh[idx]) = h2;
        *reinterpret_cast<u32*>(&g_gl[idx]) = l2;
    }
}

// ---------------------------------------------------------------------------
// Kernel 2: BN stats -> affine coefs
// ---------------------------------------------------------------------------
__global__ __launch_bounds__(256)
void stats_kernel(const float* __restrict__ gq, const float* __restrict__ betaq,
                  const float* __restrict__ gk, const float* __restrict__ betak) {
    int ch    = blockIdx.x & 63;
    int which = blockIdx.x >> 6;
    const float* y = which ? g_yk : g_yq;
    int tid = threadIdx.x;
    float s = 0.f, sq = 0.f;
    for (int n = 0; n < NB; n++) {
        const float4* row = (const float4*)(y + (size_t)n*CHW + (size_t)ch*HW);
        for (int p = tid; p < 1024; p += 256) {
            float4 v = row[p];
            s  += (v.x + v.y) + (v.z + v.w);
            sq += (v.x*v.x + v.y*v.y) + (v.z*v.z + v.w*v.w);
        }
    }
    __shared__ float rs[256], rq[256];
    rs[tid] = s; rq[tid] = sq;
    __syncthreads();
    for (int st = 128; st > 0; st >>= 1) {
        if (tid < st) { rs[tid] += rs[tid+st]; rq[tid] += rq[tid+st]; }
        __syncthreads();
    }
    if (tid == 0) {
        const float invn = 1.0f / (NB * HW);
        float mean = rs[0] * invn;
        float var  = rq[0] * invn - mean*mean;
        float g = which ? gk[ch]    : gq[ch];
        float b = which ? betak[ch] : betaq[ch];
        float a = g * rsqrtf(var + 1e-5f);
        g_aff[which*128 + ch]      = a;
        g_aff[which*128 + 64 + ch] = b - mean*a;
    }
}

// ---------------------------------------------------------------------------
// Kernel 2.5: BN affine + relu; Q -> fp16 hi/lo, K -> fp16; transpose to [n][p][c]
// ---------------------------------------------------------------------------
__global__ __launch_bounds__(256)
void prep_kernel() {
    extern __shared__ u16 sp[];
    u16* sQh = sp;
    u16* sQl = sp + 8384;
    u16* sK  = sp + 16768;
    int tid = threadIdx.x;
    int n = blockIdx.y, p0 = blockIdx.x * 128;
    size_t nb = (size_t)n*CHW;

    for (int i = tid; i < 2048; i += 256) {
        int c = i >> 5, j = i & 31;
        float4 vq = *(const float4*)&g_yq[nb + (size_t)c*HW + p0 + 4*j];
        float4 vk = *(const float4*)&g_yk[nb + (size_t)c*HW + p0 + 4*j];
        float aq = g_aff[c], bqv = g_aff[64+c];
        float ak = g_aff[128+c], bkv = g_aff[192+c];
        float q0f = fmaxf(0.f, aq*vq.x + bqv), q1f = fmaxf(0.f, aq*vq.y + bqv);
        float q2f = fmaxf(0.f, aq*vq.z + bqv), q3f = fmaxf(0.f, aq*vq.w + bqv);
        float k0f = fmaxf(0.f, ak*vk.x + bkv), k1f = fmaxf(0.f, ak*vk.y + bkv);
        float k2f = fmaxf(0.f, ak*vk.z + bkv), k3f = fmaxf(0.f, ak*vk.w + bkv);
        int base = c*131 + 4*j;
        u32 h2, l2;
        split2h(q0f, q1f, h2, l2);
        sQh[base]   = (u16)h2; sQh[base+1] = (u16)(h2>>16);
        sQl[base]   = (u16)l2; sQl[base+1] = (u16)(l2>>16);
        split2h(q2f, q3f, h2, l2);
        sQh[base+2] = (u16)h2; sQh[base+3] = (u16)(h2>>16);
        sQl[base+2] = (u16)l2; sQl[base+3] = (u16)(l2>>16);
        u32 kk = pack2h(k0f, k1f);
        sK[base]   = (u16)kk; sK[base+1] = (u16)(kk>>16);
        kk = pack2h(k2f, k3f);
        sK[base+2] = (u16)kk; sK[base+3] = (u16)(kk>>16);
    }
    __syncthreads();

    u32* oqh = (u32*)g_q16h; u32* oql = (u32*)g_q16l; u32* ok = (u32*)g_k16;
    for (int i = tid; i < 4096; i += 256) {
        int p = i >> 5, c2 = i & 31;
        u32 idx = (u32)(n*4096 + p0 + p)*32 + c2;
        u32 a, b;
        a = sQh[(2*c2)*131 + p]; b = sQh[(2*c2+1)*131 + p]; oqh[idx] = a | (b<<16);
        a = sQl[(2*c2)*131 + p]; b = sQl[(2*c2+1)*131 + p]; oql[idx] = a | (b<<16);
        a = sK [(2*c2)*131 + p]; b = sK [(2*c2+1)*131 + p]; ok [idx] = a | (b<<16);
    }
}

// ---------------------------------------------------------------------------
// Kernel 3: flash attention. S: fp16 2-pass (Q split, K single).
// ctx: bf16 3-pass (P split bf16 — range-safe, G split bf16).
// 4 smem buffers, cross-tile pipelining (R10 structure).
// Buffer (27648 B): K[64key][72u16]@0, Gh[64c][72u16]@9216, Gl@18432
// ---------------------------------------------------------------------------
#define G_OFF   9216u
#define GLO_OFF 9216u
#define BUFSZ   27648u
#define ATTN_SMEM (4*27648)
#define ESHIFT  20.0f

__device__ __forceinline__ void load_kg(u32 buf, int n, int k0, int tid) {
    const u16* kk = g_k16 + (size_t)(n*4096 + k0)*64;
    const u16* gh = g_gh + (size_t)n*CHW + k0;
    const u16* gl = g_gl + (size_t)n*CHW + k0;
    #pragma unroll
    for (int ii = 0; ii < 2; ii++) {
        int i = tid + ii*256;
        int row = i >> 3, seg = i & 7;
        cpasync16(buf + (u32)row*144u + (u32)seg*16u, kk + row*64 + seg*8);
        u32 sg = buf + G_OFF + (u32)row*144u + (u32)seg*16u;
        cpasync16(sg,           gh + (size_t)row*HW + seg*8);
        cpasync16(sg + GLO_OFF, gl + (size_t)row*HW + seg*8);
    }
}

__global__ __launch_bounds__(256, 1)
void attn_kernel(float* __restrict__ out) {
    extern __shared__ char smc[];
    u32 sb = smem_u32(smc);
    const int tid = threadIdx.x;
    const int w = tid >> 5, lane = tid & 31;
    const int n = blockIdx.y, q0 = blockIdx.x * 128;
    const size_t nb = (size_t)n * CHW;
    const int r0 = lane >> 2, cb = (lane & 3) * 2;

    // ---- Q fp16 fragments straight from gmem ----
    u32 qh[4][4], ql[4][4];
    {
        const u16* qbh = g_q16h + (size_t)(n*4096 + q0 + w*16)*64;
        const u16* qbl = g_q16l + (size_t)(n*4096 + q0 + w*16)*64;
        #pragma unroll
        for (int kc = 0; kc < 4; kc++)
            #pragma unroll
            for (int r = 0; r < 4; r++) {
                int off = (r0 + (r & 1)*8)*64 + cb + (r >> 1)*8 + kc*16;
                qh[kc][r] = *(const u32*)(qbh + off);
                ql[kc][r] = *(const u32*)(qbl + off);
            }
    }

    float ctx[8][4];
    #pragma unroll
    for (int t = 0; t < 8; t++)
        #pragma unroll
        for (int r = 0; r < 4; r++) ctx[t][r] = 0.f;
    float lA = 0.f, lB = 0.f;
    float sacc[8][4];
    u32 pfh0[4][4], pfl0[4][4], pfh1[4][4], pfl1[4][4];

    const u32 lm_row = (u32)(lane & 15);
    const u32 lm_hi  = (u32)(lane >> 4) * 16u;

    // ---- S = Q·K^T fp16 (2 passes, 4 chains) ----
    auto do_smma = [&](u32 cur) {
        #pragma unroll
        for (int t = 0; t < 8; t++)
            #pragma unroll
            for (int r = 0; r < 4; r++) sacc[t][r] = 0.f;
        #pragma unroll
        for (int ntp = 0; ntp < 2; ntp++) {
            u32 ra0 = cur + ((2*ntp)*16u   + lm_row)*144u + lm_hi;
            u32 ra1 = cur + ((2*ntp+1)*16u + lm_row)*144u + lm_hi;
            float* s0 = sacc[4*ntp];
            float* s1 = sacc[4*ntp+1];
            float* s2 = sacc[4*ntp+2];
            float* s3 = sacc[4*ntp+3];
            #pragma unroll
            for (int kc = 0; kc < 4; kc++) {
                u32 b0[4], b1[4];
                ldsm4(b0, ra0 + kc*32u);
                ldsm4(b1, ra1 + kc*32u);
                mma16816h(s0, qh[kc], b0[0], b0[2]);
                mma16816h(s1, qh[kc], b0[1], b0[3]);
                mma16816h(s2, qh[kc], b1[0], b1[2]);
                mma16816h(s3, qh[kc], b1[1], b1[3]);
                mma16816h(s0, ql[kc], b0[0], b0[2]);
                mma16816h(s1, ql[kc], b0[1], b0[3]);
                mma16816h(s2, ql[kc], b1[0], b1[2]);
                mma16816h(s3, ql[kc], b1[1], b1[3]);
            }
        }
    };

    // ---- epilogue piece: consumes sacc[chunk] -> bf16 P set ----
    auto epi_piece = [&](int chunk, u32 (&phC)[4][4], u32 (&plC)[4][4]) {
        float p0 = __expf(sacc[chunk][0] - ESHIFT);
        float p1 = __expf(sacc[chunk][1] - ESHIFT);
        float p2 = __expf(sacc[chunk][2] - ESHIFT);
        float p3 = __expf(sacc[chunk][3] - ESHIFT);
        lA += p0 + p1; lB += p2 + p3;
        int j2 = chunk >> 1, half = chunk & 1;
        u32 h2, l2;
        split2(p0, p1, h2, l2);
        phC[j2][2*half]   = h2; plC[j2][2*half]   = l2;
        split2(p2, p3, h2, l2);
        phC[j2][2*half+1] = h2; plC[j2][2*half+1] = l2;
    };

    // ---- ctx(prev) bf16 3-pass interleaved with epilogue(cur) ----
    auto do_ctx_epi = [&](u32 gslot, u32 (&phP)[4][4], u32 (&plP)[4][4],
                          u32 (&phC)[4][4], u32 (&plC)[4][4]) {
        #pragma unroll
        for (int cgp = 0; cgp < 2; cgp++) {
            u32 ra0 = gslot + G_OFF + ((2*cgp)*16u   + lm_row)*144u + lm_hi;
            u32 ra1 = gslot + G_OFF + ((2*cgp+1)*16u + lm_row)*144u + lm_hi;
            float* c0 = ctx[4*cgp];
            float* c1 = ctx[4*cgp+1];
            float* c2 = ctx[4*cgp+2];
            float* c3 = ctx[4*cgp+3];
            #pragma unroll
            for (int j = 0; j < 4; j++) {
                u32 b0h[4], b0l[4], b1h[4], b1l[4];
                ldsm4(b0h, ra0 + j*32u);
                ldsm4(b1h, ra1 + j*32u);
                ldsm4(b0l, ra0 + GLO_OFF + j*32u);
                ldsm4(b1l, ra1 + GLO_OFF + j*32u);
                mma16816(c0, phP[j], b0h[0], b0h[2]);
                mma16816(c1, phP[j], b0h[1], b0h[3]);
                mma16816(c2, phP[j], b1h[0], b1h[2]);
                mma16816(c3, phP[j], b1h[1], b1h[3]);
                mma16816(c0, phP[j], b0l[0], b0l[2]);
                mma16816(c1, phP[j], b0l[1], b0l[3]);
                mma16816(c2, phP[j], b1l[0], b1l[2]);
                mma16816(c3, phP[j], b1l[1], b1l[3]);
                mma16816(c0, plP[j], b0h[0], b0h[2]);
                mma16816(c1, plP[j], b0h[1], b0h[3]);
                mma16816(c2, plP[j], b1h[0], b1h[2]);
                mma16816(c3, plP[j], b1h[1], b1h[3]);
                epi_piece(cgp*4 + j, phC, plC);
            }
        }
    };

    auto do_ctx = [&](u32 gslot, u32 (&phP)[4][4], u32 (&plP)[4][4]) {
        #pragma unroll
        for (int cgp = 0; cgp < 2; cgp++) {
            u32 ra0 = gslot + G_OFF + ((2*cgp)*16u   + lm_row)*144u + lm_hi;
            u32 ra1 = gslot + G_OFF + ((2*cgp+1)*16u + lm_row)*144u + lm_hi;
            float* c0 = ctx[4*cgp];
            float* c1 = ctx[4*cgp+1];
            float* c2 = ctx[4*cgp+2];
            float* c3 = ctx[4*cgp+3];
            #pragma unroll
            for (int j = 0; j < 4; j++) {
                u32 b0h[4], b0l[4], b1h[4], b1l[4];
                ldsm4(b0h, ra0 + j*32u);
                ldsm4(b1h, ra1 + j*32u);
                ldsm4(b0l, ra0 + GLO_OFF + j*32u);
                ldsm4(b1l, ra1 + GLO_OFF + j*32u);
                mma16816(c0, phP[j], b0h[0], b0h[2]);
                mma16816(c1, phP[j], b0h[1], b0h[3]);
                mma16816(c2, phP[j], b1h[0], b1h[2]);
                mma16816(c3, phP[j], b1h[1], b1h[3]);
                mma16816(c0, phP[j], b0l[0], b0l[2]);
                mma16816(c1, phP[j], b0l[1], b0l[3]);
                mma16816(c2, phP[j], b1l[0], b1l[2]);
                mma16816(c3, phP[j], b1l[1], b1l[3]);
                mma16816(c0, plP[j], b0h[0], b0h[2]);
                mma16816(c1, plP[j], b0h[1], b0h[3]);
                mma16816(c2, plP[j], b1h[0], b1h[2]);
                mma16816(c3, plP[j], b1h[1], b1h[3]);
            }
        }
    };

    // prologue: load tiles 0,1; S(0); epilogue(0) -> set0
    load_kg(sb,          n, 0,  tid); CP_COMMIT();
    load_kg(sb + BUFSZ,  n, 64, tid); CP_COMMIT();
    CP_WAIT(1);
    __syncthreads();
    do_smma(sb);
    #pragma unroll
    for (int chunk = 0; chunk < 8; chunk++) epi_piece(chunk, pfh0, pfl0);

    auto body = [&](int t, u32 (&phP)[4][4], u32 (&plP)[4][4],
                    u32 (&phC)[4][4], u32 (&plC)[4][4]) {
        if (t < 63) {
            load_kg(sb + (u32)((t + 1) & 3) * BUFSZ, n, (t + 1) * 64, tid);
            CP_COMMIT();
            CP_WAIT(1);
        } else {
            CP_WAIT(0);
        }
        __syncthreads();
        do_smma(sb + (u32)(t & 3) * BUFSZ);
        do_ctx_epi(sb + (u32)((t - 1) & 3) * BUFSZ, phP, plP, phC, plC);
    };

    for (int t = 1; t + 1 < 64; t += 2) {
        body(t,     pfh0, pfl0, pfh1, pfl1);
        body(t + 1, pfh1, pfl1, pfh0, pfl0);
    }
    body(63, pfh0, pfl0, pfh1, pfl1);
    do_ctx(sb + 3u * BUFSZ, pfh1, pfl1);   // drain ctx(63): G slot 3

    // ---- finalize ----
    lA += __shfl_xor_sync(0xffffffffu, lA, 1);
    lA += __shfl_xor_sync(0xffffffffu, lA, 2);
    lB += __shfl_xor_sync(0xffffffffu, lB, 1);
    lB += __shfl_xor_sync(0xffffffffu, lB, 2);
    float invA = 1.0f / lA, invB = 1.0f / lB;

    // Os overlaps slots 0/1 only; after the final barrier warps read slots 2/3.
    float* Os = (float*)smc;   // [64][132]
    #pragma unroll
    for (int t = 0; t < 8; t++) {
        #pragma unroll
        for (int r = 0; r < 4; r++) {
            int row = r0 + 8*(r >> 1);
            int c   = t*8 + cb + (r & 1);
            Os[c*132 + w*16 + row] = ctx[t][r] * ((r >> 1) ? invB : invA);
        }
    }
    __syncthreads();
    for (int i = tid; i < 8192; i += 256) {
        int c = i >> 7, q = i & 127;
        out[nb + (size_t)c*HW + q0 + q] = Os[c*132 + q];
    }
}

// ---------------------------------------------------------------------------
extern "C" void kernel_launch(void* const* d_in, const int* in_sizes, int n_in,
                              void* d_out, int out_size) {
    const float* x     = (const float*)d_in[0];
    const float* h0    = (const float*)d_in[1];
    const float* h1    = (const float*)d_in[2];
    const float* Wq    = (const float*)d_in[3];
    const float* bq    = (const float*)d_in[4];
    const float* gq    = (const float*)d_in[5];
    const float* betaq = (const float*)d_in[6];
    const float* Wk    = (const float*)d_in[7];
    const float* bk    = (const float*)d_in[8];
    const float* gk    = (const float*)d_in[9];
    const float* betak = (const float*)d_in[10];
    const float* Wv    = (const float*)d_in[11];
    const float* bv    = (const float*)d_in[12];
    float* out = (float*)d_out;

    const int proj_smem = 14336 * 4;
    const int prep_smem = 25152 * 2 + 64;
    cudaFuncSetAttribute(proj_kernel, cudaFuncAttributeMaxDynamicSharedMemorySize, proj_smem);
    cudaFuncSetAttribute(prep_kernel, cudaFuncAttributeMaxDynamicSharedMemorySize, prep_smem);
    cudaFuncSetAttribute(attn_kernel, cudaFuncAttributeMaxDynamicSharedMemorySize, ATTN_SMEM);

    proj_kernel<<<512, 256, proj_smem>>>(x, h0, h1, Wq, bq, Wk, bk, Wv, bv);
    stats_kernel<<<128, 256>>>(gq, betaq, gk, betak);
    prep_kernel<<<dim3(32, NB), 256, prep_smem>>>();
    attn_kernel<<<dim3(32, NB), 256, ATTN_SMEM>>>(out);
}

// round 13
// speedup vs baseline: 1.3285x; 1.0783x over previous
#include <cuda_runtime.h>
#include <cuda_fp16.h>
#include <math.h>
#include <cstdint>

#define CH    64
#define HW    4096
#define NB    4
#define CHW   (CH*HW)
#define TOTAL (NB*CHW)

typedef unsigned long long ull;
typedef unsigned int       u32;
typedef unsigned short     u16;

// ------------------------- device scratch ----------------------------------
__device__ __align__(16) float g_yq[TOTAL];   // [n][c][p]
__device__ __align__(16) float g_yk[TOTAL];
__device__ float               g_aff[4*CH];
__device__ __align__(16) u16   g_g16[TOTAL];  // gated value fp16 [n][c][p]
__device__ __align__(16) u16   g_q16h[TOTAL]; // Q' fp16 hi [n][p][c]
__device__ __align__(16) u16   g_q16l[TOTAL]; // Q' fp16 lo
__device__ __align__(16) u16   g_k16h[TOTAL]; // K' fp16 hi [n][p][c]
__device__ __align__(16) u16   g_k16l[TOTAL]; // K' fp16 lo

// ------------------------------ helpers ------------------------------------
__device__ __forceinline__ ull pk2(float x, float y) {
    ull r; asm("mov.b64 %0,{%1,%2};" : "=l"(r) : "f"(x), "f"(y)); return r;
}
__device__ __forceinline__ void upk2(ull v, float& x, float& y) {
    asm("mov.b64 {%0,%1},%2;" : "=f"(x), "=f"(y) : "l"(v));
}
__device__ __forceinline__ void fma2(ull& d, ull a, ull b) {
    asm("fma.rn.f32x2 %0,%1,%2,%0;" : "+l"(d) : "l"(a), "l"(b));
}
__device__ __forceinline__ ull add2_(ull a, ull b) {
    ull r; asm("add.rn.f32x2 %0,%1,%2;" : "=l"(r) : "l"(a), "l"(b)); return r;
}
__device__ __forceinline__ ull mul2_(ull a, ull b) {
    ull r; asm("mul.rn.f32x2 %0,%1,%2;" : "=l"(r) : "l"(a), "l"(b)); return r;
}
__device__ __forceinline__ ull ld2(const float* p) { return *reinterpret_cast<const ull*>(p); }

// split fp32 pair (a,b) -> fp16x2 hi + fp16x2 lo (low 16 bits = a)
__device__ __forceinline__ void split2h(float a, float b, u32& h2, u32& l2) {
    __half2 h = __floats2half2_rn(a, b);
    float2 f = __half22float2(h);
    __half2 l = __floats2half2_rn(a - f.x, b - f.y);
    h2 = *reinterpret_cast<u32*>(&h);
    l2 = *reinterpret_cast<u32*>(&l);
}
__device__ __forceinline__ u32 pack2h(float a, float b) {
    __half2 h = __floats2half2_rn(a, b);
    return *reinterpret_cast<u32*>(&h);
}
__device__ __forceinline__ u32 smem_u32(const void* p) {
    u32 a; asm("{ .reg .u64 t; cvta.to.shared.u64 t, %1; cvt.u32.u64 %0, t; }" : "=r"(a) : "l"(p));
    return a;
}
__device__ __forceinline__ void cpasync16(u32 s, const void* g) {
    asm volatile("cp.async.cg.shared.global [%0], [%1], 16;" :: "r"(s), "l"(g) : "memory");
}
#define CP_COMMIT() asm volatile("cp.async.commit_group;" ::: "memory")
#define CP_WAIT(n)  asm volatile("cp.async.wait_group %0;" :: "n"(n) : "memory")

__device__ __forceinline__ void ldsm4(u32* t, u32 addr) {
    asm volatile("ldmatrix.sync.aligned.m8n8.x4.shared.b16 {%0,%1,%2,%3}, [%4];"
        : "=r"(t[0]), "=r"(t[1]), "=r"(t[2]), "=r"(t[3]) : "r"(addr));
}
// D += A * B   fp16 in, f32 accum
__device__ __forceinline__ void mma16816h(float* d, const u32* a, u32 b0, u32 b1) {
    asm volatile("mma.sync.aligned.m16n8k16.row.col.f32.f16.f16.f32 "
        "{%0,%1,%2,%3}, {%4,%5,%6,%7}, {%8,%9}, {%0,%1,%2,%3};"
        : "+f"(d[0]), "+f"(d[1]), "+f"(d[2]), "+f"(d[3])
        : "r"(a[0]), "r"(a[1]), "r"(a[2]), "r"(a[3]), "r"(b0), "r"(b1));
}

// ---------------------------------------------------------------------------
// Kernel 1: projections + gated value fp16. grid 512, 32 positions/blk
// ---------------------------------------------------------------------------
__global__ __launch_bounds__(256)
void proj_kernel(const float* __restrict__ x,
                 const float* __restrict__ h0,
                 const float* __restrict__ h1,
                 const float* __restrict__ Wq, const float* __restrict__ bq,
                 const float* __restrict__ Wk, const float* __restrict__ bk,
                 const float* __restrict__ Wv, const float* __restrict__ bv) {
    extern __shared__ float sm[];
    float* sWq = sm;
    float* sWk = sm + 4096;
    float* sWv = sm + 8192;
    float* xs  = sm + 12288;   // [64][32]

    int tid = threadIdx.x;
    for (int i = tid; i < 4096; i += 256) {
        sWq[i] = Wq[i]; sWk[i] = Wk[i]; sWv[i] = Wv[i];
    }
    int P0 = blockIdx.x * 32;
    int n  = P0 >> 12;
    int p0 = P0 & (HW - 1);
    const float* xb = x + (size_t)n*CHW + p0;
    for (int i = tid; i < 2048; i += 256) {
        int c = i >> 5, pp = i & 31;
        xs[c*32 + pp] = xb[(size_t)c*HW + pp];
    }
    __syncthreads();

    int ty = tid >> 4, tx = tid & 15;
    ull aq2[4], ak2[4], av2[4];
    #pragma unroll
    for (int io = 0; io < 4; io++) {
        int o = ty + 16*io;
        aq2[io] = pk2(bq[o], bq[o]);
        ak2[io] = pk2(bk[o], bk[o]);
        av2[io] = pk2(bv[o], bv[o]);
    }
    #pragma unroll 4
    for (int c = 0; c < 64; c++) {
        ull xv = ld2(&xs[c*32 + 2*tx]);
        #pragma unroll
        for (int io = 0; io < 4; io++) {
            int o = ty + 16*io;
            float wqs = sWq[o*64+c], wks = sWk[o*64+c], wvs = sWv[o*64+c];
            fma2(aq2[io], pk2(wqs,wqs), xv);
            fma2(ak2[io], pk2(wks,wks), xv);
            fma2(av2[io], pk2(wvs,wvs), xv);
        }
    }
    size_t base = (size_t)n*CHW + p0;
    #pragma unroll
    for (int io = 0; io < 4; io++) {
        int o = ty + 16*io;
        size_t idx = base + (size_t)o*HW + 2*tx;
        *reinterpret_cast<ull*>(&g_yq[idx]) = aq2[io];
        *reinterpret_cast<ull*>(&g_yk[idx]) = ak2[io];
        ull h0p = *reinterpret_cast<const ull*>(&h0[idx]);
        ull h1p = *reinterpret_cast<const ull*>(&h1[idx]);
        ull gv  = mul2_(add2_(h0p, h1p), av2[io]);
        float ga, gb; upk2(gv, ga, gb);
        *reinterpret_cast<u32*>(&g_g16[idx]) = pack2h(ga, gb);
    }
}

// ---------------------------------------------------------------------------
// Kernel 2: BN stats -> affine coefs
// ---------------------------------------------------------------------------
__global__ __launch_bounds__(256)
void stats_kernel(const float* __restrict__ gq, const float* __restrict__ betaq,
                  const float* __restrict__ gk, const float* __restrict__ betak) {
    int ch    = blockIdx.x & 63;
    int which = blockIdx.x >> 6;
    const float* y = which ? g_yk : g_yq;
    int tid = threadIdx.x;
    float s = 0.f, sq = 0.f;
    for (int n = 0; n < NB; n++) {
        const float4* row = (const float4*)(y + (size_t)n*CHW + (size_t)ch*HW);
        for (int p = tid; p < 1024; p += 256) {
            float4 v = row[p];
            s  += (v.x + v.y) + (v.z + v.w);
            sq += (v.x*v.x + v.y*v.y) + (v.z*v.z + v.w*v.w);
        }
    }
    __shared__ float rs[256], rq[256];
    rs[tid] = s; rq[tid] = sq;
    __syncthreads();
    for (int st = 128; st > 0; st >>= 1) {
        if (tid < st) { rs[tid] += rs[tid+st]; rq[tid] += rq[tid+st]; }
        __syncthreads();
    }
    if (tid == 0) {
        const float invn = 1.0f / (NB * HW);
        float mean = rs[0] * invn;
        float var  = rq[0] * invn - mean*mean;
        float g = which ? gk[ch]    : gq[ch];
        float b = which ? betak[ch] : betaq[ch];
        float a = g * rsqrtf(var + 1e-5f);
        g_aff[which*128 + ch]      = a;
        g_aff[which*128 + 64 + ch] = b - mean*a;
    }
}

// ---------------------------------------------------------------------------
// Kernel 2.5: BN affine + relu; Q,K -> fp16 hi/lo; transpose to [n][p][c]
// ---------------------------------------------------------------------------
__global__ __launch_bounds__(256)
void prep_kernel() {
    extern __shared__ u16 sp[];
    u16* sQh = sp;
    u16* sQl = sp + 8384;
    u16* sKh = sp + 16768;
    u16* sKl = sp + 25152;
    int tid = threadIdx.x;
    int n = blockIdx.y, p0 = blockIdx.x * 128;
    size_t nb = (size_t)n*CHW;

    for (int i = tid; i < 2048; i += 256) {
        int c = i >> 5, j = i & 31;
        float4 vq = *(const float4*)&g_yq[nb + (size_t)c*HW + p0 + 4*j];
        float4 vk = *(const float4*)&g_yk[nb + (size_t)c*HW + p0 + 4*j];
        float aq = g_aff[c], bqv = g_aff[64+c];
        float ak = g_aff[128+c], bkv = g_aff[192+c];
        float q0f = fmaxf(0.f, aq*vq.x + bqv), q1f = fmaxf(0.f, aq*vq.y + bqv);
        float q2f = fmaxf(0.f, aq*vq.z + bqv), q3f = fmaxf(0.f, aq*vq.w + bqv);
        float k0f = fmaxf(0.f, ak*vk.x + bkv), k1f = fmaxf(0.f, ak*vk.y + bkv);
        float k2f = fmaxf(0.f, ak*vk.z + bkv), k3f = fmaxf(0.f, ak*vk.w + bkv);
        int base = c*131 + 4*j;
        u32 h2, l2;
        split2h(q0f, q1f, h2, l2);
        sQh[base]   = (u16)h2; sQh[base+1] = (u16)(h2>>16);
        sQl[base]   = (u16)l2; sQl[base+1] = (u16)(l2>>16);
        split2h(q2f, q3f, h2, l2);
        sQh[base+2] = (u16)h2; sQh[base+3] = (u16)(h2>>16);
        sQl[base+2] = (u16)l2; sQl[base+3] = (u16)(l2>>16);
        split2h(k0f, k1f, h2, l2);
        sKh[base]   = (u16)h2; sKh[base+1] = (u16)(h2>>16);
        sKl[base]   = (u16)l2; sKl[base+1] = (u16)(l2>>16);
        split2h(k2f, k3f, h2, l2);
        sKh[base+2] = (u16)h2; sKh[base+3] = (u16)(h2>>16);
        sKl[base+2] = (u16)l2; sKl[base+3] = (u16)(l2>>16);
    }
    __syncthreads();

    u32* oqh = (u32*)g_q16h; u32* oql = (u32*)g_q16l;
    u32* okh = (u32*)g_k16h; u32* okl = (u32*)g_k16l;
    for (int i = tid; i < 4096; i += 256) {
        int p = i >> 5, c2 = i & 31;
        u32 idx = (u32)(n*4096 + p0 + p)*32 + c2;
        u32 a, b;
        a = sQh[(2*c2)*131 + p]; b = sQh[(2*c2+1)*131 + p]; oqh[idx] = a | (b<<16);
        a = sQl[(2*c2)*131 + p]; b = sQl[(2*c2+1)*131 + p]; oql[idx] = a | (b<<16);
        a = sKh[(2*c2)*131 + p]; b = sKh[(2*c2+1)*131 + p]; okh[idx] = a | (b<<16);
        a = sKl[(2*c2)*131 + p]; b = sKl[(2*c2+1)*131 + p]; okl[idx] = a | (b<<16);
    }
}

// ---------------------------------------------------------------------------
// Kernel 3: flash attention. S: fp16 3-pass (error ~1e-6).
// ctx: fp16 1-pass (P fp16 via online row-max so p<=1; G fp16).
// 4 smem buffers, cross-tile pipelining.
// Buffer (27648 B): Kh[64key][72u16]@0, Kl@9216, G[64c][72u16]@18432
// ---------------------------------------------------------------------------
#define KLO_OFF 9216u
#define G_OFF   18432u
#define BUFSZ   27648u
#define ATTN_SMEM (4*27648)

__device__ __forceinline__ void load_kg(u32 buf, int n, int k0, int tid) {
    const u16* kh = g_k16h + (size_t)(n*4096 + k0)*64;
    const u16* kl = g_k16l + (size_t)(n*4096 + k0)*64;
    const u16* gg = g_g16 + (size_t)n*CHW + k0;
    #pragma unroll
    for (int ii = 0; ii < 2; ii++) {
        int i = tid + ii*256;
        int row = i >> 3, seg = i & 7;
        u32 sk = buf + (u32)row*144u + (u32)seg*16u;
        cpasync16(sk,           kh + row*64 + seg*8);
        cpasync16(sk + KLO_OFF, kl + row*64 + seg*8);
        cpasync16(buf + G_OFF + (u32)row*144u + (u32)seg*16u,
                  gg + (size_t)row*HW + seg*8);
    }
}

__global__ __launch_bounds__(256, 1)
void attn_kernel(float* __restrict__ out) {
    extern __shared__ char smc[];
    u32 sb = smem_u32(smc);
    const int tid = threadIdx.x;
    const int w = tid >> 5, lane = tid & 31;
    const int n = blockIdx.y, q0 = blockIdx.x * 128;
    const size_t nb = (size_t)n * CHW;
    const int r0 = lane >> 2, cb = (lane & 3) * 2;

    // ---- Q fp16 fragments straight from gmem ----
    u32 qh[4][4], ql[4][4];
    {
        const u16* qbh = g_q16h + (size_t)(n*4096 + q0 + w*16)*64;
        const u16* qbl = g_q16l + (size_t)(n*4096 + q0 + w*16)*64;
        #pragma unroll
        for (int kc = 0; kc < 4; kc++)
            #pragma unroll
            for (int r = 0; r < 4; r++) {
                int off = (r0 + (r & 1)*8)*64 + cb + (r >> 1)*8 + kc*16;
                qh[kc][r] = *(const u32*)(qbh + off);
                ql[kc][r] = *(const u32*)(qbl + off);
            }
    }

    float ctx[8][4];
    #pragma unroll
    for (int t = 0; t < 8; t++)
        #pragma unroll
        for (int r = 0; r < 4; r++) ctx[t][r] = 0.f;
    float lA = 0.f, lB = 0.f;
    float mA = -1e30f, mB = -1e30f;
    float lsA = 0.f, lsB = 0.f, scA = 0.f, scB = 0.f;
    float sacc[8][4];
    u32 pf0[4][4], pf1[4][4];

    const u32 lm_row = (u32)(lane & 15);
    const u32 lm_hi  = (u32)(lane >> 4) * 16u;

    // ---- S = Q·K^T fp16 3-pass (Qh·Kh + Ql·Kh + Qh·Kl), 4 chains ----
    auto do_smma = [&](u32 cur) {
        #pragma unroll
        for (int t = 0; t < 8; t++)
            #pragma unroll
            for (int r = 0; r < 4; r++) sacc[t][r] = 0.f;
        #pragma unroll
        for (int ntp = 0; ntp < 2; ntp++) {
            u32 ra0 = cur + ((2*ntp)*16u   + lm_row)*144u + lm_hi;
            u32 ra1 = cur + ((2*ntp+1)*16u + lm_row)*144u + lm_hi;
            float* s0 = sacc[4*ntp];
            float* s1 = sacc[4*ntp+1];
            float* s2 = sacc[4*ntp+2];
            float* s3 = sacc[4*ntp+3];
            #pragma unroll
            for (int kc = 0; kc < 4; kc++) {
                u32 b0h[4], b0l[4], b1h[4], b1l[4];
                ldsm4(b0h, ra0 + kc*32u);
                ldsm4(b1h, ra1 + kc*32u);
                ldsm4(b0l, ra0 + KLO_OFF + kc*32u);
                ldsm4(b1l, ra1 + KLO_OFF + kc*32u);
                mma16816h(s0, qh[kc], b0h[0], b0h[2]);
                mma16816h(s1, qh[kc], b0h[1], b0h[3]);
                mma16816h(s2, qh[kc], b1h[0], b1h[2]);
                mma16816h(s3, qh[kc], b1h[1], b1h[3]);
                mma16816h(s0, ql[kc], b0h[0], b0h[2]);
                mma16816h(s1, ql[kc], b0h[1], b0h[3]);
                mma16816h(s2, ql[kc], b1h[0], b1h[2]);
                mma16816h(s3, ql[kc], b1h[1], b1h[3]);
                mma16816h(s0, qh[kc], b0l[0], b0l[2]);
                mma16816h(s1, qh[kc], b0l[1], b0l[3]);
                mma16816h(s2, qh[kc], b1l[0], b1l[2]);
                mma16816h(s3, qh[kc], b1l[1], b1l[3]);
            }
        }
    };

    // ---- online row-max update: tile max -> new m, scale factors ----
    auto rowmax = [&]() {
        float tA = sacc[0][0], tB = sacc[0][2];
        #pragma unroll
        for (int t = 0; t < 8; t++) {
            tA = fmaxf(tA, fmaxf(sacc[t][0], sacc[t][1]));
            tB = fmaxf(tB, fmaxf(sacc[t][2], sacc[t][3]));
        }
        tA = fmaxf(tA, __shfl_xor_sync(0xffffffffu, tA, 1));
        tA = fmaxf(tA, __shfl_xor_sync(0xffffffffu, tA, 2));
        tB = fmaxf(tB, __shfl_xor_sync(0xffffffffu, tB, 1));
        tB = fmaxf(tB, __shfl_xor_sync(0xffffffffu, tB, 2));
        float nmA = fmaxf(mA, tA), nmB = fmaxf(mB, tB);
        scA = __expf(mA - nmA); scB = __expf(mB - nmB);
        mA = nmA; mB = nmB;
        lsA = 0.f; lsB = 0.f;
    };

    // ---- epilogue piece: consumes sacc[chunk] -> fp16 P set (p <= 1) ----
    auto epi_piece = [&](int chunk, u32 (&pfC)[4][4]) {
        float p0 = __expf(sacc[chunk][0] - mA);
        float p1 = __expf(sacc[chunk][1] - mA);
        float p2 = __expf(sacc[chunk][2] - mB);
        float p3 = __expf(sacc[chunk][3] - mB);
        lsA += p0 + p1; lsB += p2 + p3;
        int j2 = chunk >> 1, half = chunk & 1;
        pfC[j2][2*half]   = pack2h(p0, p1);
        pfC[j2][2*half+1] = pack2h(p2, p3);
    };

    // ---- ctx(prev) fp16 1-pass interleaved with epilogue(cur) ----
    auto do_ctx_epi = [&](u32 gslot, u32 (&pfP)[4][4], u32 (&pfC)[4][4]) {
        #pragma unroll
        for (int cgp = 0; cgp < 2; cgp++) {
            u32 ra0 = gslot + G_OFF + ((2*cgp)*16u   + lm_row)*144u + lm_hi;
            u32 ra1 = gslot + G_OFF + ((2*cgp+1)*16u + lm_row)*144u + lm_hi;
            float* c0 = ctx[4*cgp];
            float* c1 = ctx[4*cgp+1];
            float* c2 = ctx[4*cgp+2];
            float* c3 = ctx[4*cgp+3];
            #pragma unroll
            for (int j = 0; j < 4; j++) {
                u32 b0[4], b1[4];
                ldsm4(b0, ra0 + j*32u);
                ldsm4(b1, ra1 + j*32u);
                mma16816h(c0, pfP[j], b0[0], b0[2]);
                mma16816h(c1, pfP[j], b0[1], b0[3]);
                mma16816h(c2, pfP[j], b1[0], b1[2]);
                mma16816h(c3, pfP[j], b1[1], b1[3]);
                epi_piece(cgp*4 + j, pfC);
            }
        }
    };

    auto do_ctx = [&](u32 gslot, u32 (&pfP)[4][4]) {
        #pragma unroll
        for (int cgp = 0; cgp < 2; cgp++) {
            u32 ra0 = gslot + G_OFF + ((2*cgp)*16u   + lm_row)*144u + lm_hi;
            u32 ra1 = gslot + G_OFF + ((2*cgp+1)*16u + lm_row)*144u + lm_hi;
            float* c0 = ctx[4*cgp];
            float* c1 = ctx[4*cgp+1];
            float* c2 = ctx[4*cgp+2];
            float* c3 = ctx[4*cgp+3];
            #pragma unroll
            for (int j = 0; j < 4; j++) {
                u32 b0[4], b1[4];
                ldsm4(b0, ra0 + j*32u);
                ldsm4(b1, ra1 + j*32u);
                mma16816h(c0, pfP[j], b0[0], b0[2]);
                mma16816h(c1, pfP[j], b0[1], b0[3]);
                mma16816h(c2, pfP[j], b1[0], b1[2]);
                mma16816h(c3, pfP[j], b1[1], b1[3]);
            }
        }
    };

    // rescale ctx & l to the new max scale (call AFTER ctx(prev) accumulation)
    auto rescale = [&]() {
        #pragma unroll
        for (int t = 0; t < 8; t++) {
            ctx[t][0] *= scA; ctx[t][1] *= scA;
            ctx[t][2] *= scB; ctx[t][3] *= scB;
        }
        lA = lA*scA + lsA;
        lB = lB*scB + lsB;
    };

    // prologue: load tiles 0,1; S(0); rowmax; epilogue(0) -> pf0
    load_kg(sb,          n, 0,  tid); CP_COMMIT();
    load_kg(sb + BUFSZ,  n, 64, tid); CP_COMMIT();
    CP_WAIT(1);
    __syncthreads();
    do_smma(sb);
    rowmax();
    #pragma unroll
    for (int chunk = 0; chunk < 8; chunk++) epi_piece(chunk, pf0);
    rescale();

    auto body = [&](int t, u32 (&pfP)[4][4], u32 (&pfC)[4][4]) {
        if (t < 63) {
            load_kg(sb + (u32)((t + 1) & 3) * BUFSZ, n, (t + 1) * 64, tid);
            CP_COMMIT();
            CP_WAIT(1);
        } else {
            CP_WAIT(0);
        }
        __syncthreads();
        do_smma(sb + (u32)(t & 3) * BUFSZ);
        rowmax();
        do_ctx_epi(sb + (u32)((t - 1) & 3) * BUFSZ, pfP, pfC);
        rescale();
    };

    for (int t = 1; t + 1 < 64; t += 2) {
        body(t,     pf0, pf1);
        body(t + 1, pf1, pf0);
    }
    body(63, pf0, pf1);
    do_ctx(sb + 3u * BUFSZ, pf1);   // drain ctx(63): G slot 63&3=3

    // ---- finalize ----
    lA += __shfl_xor_sync(0xffffffffu, lA, 1);
    lA += __shfl_xor_sync(0xffffffffu, lA, 2);
    lB += __shfl_xor_sync(0xffffffffu, lB, 1);
    lB += __shfl_xor_sync(0xffffffffu, lB, 2);
    float invA = 1.0f / lA, invB = 1.0f / lB;

    // Os overlaps slots 0/1 only; drain reads slot 3 — disjoint.
    float* Os = (float*)smc;   // [64][132]
    #pragma unroll
    for (int t = 0; t < 8; t++) {
        #pragma unroll
        for (int r = 0; r < 4; r++) {
            int row = r0 + 8*(r >> 1);
            int c   = t*8 + cb + (r & 1);
            Os[c*132 + w*16 + row] = ctx[t][r] * ((r >> 1) ? invB : invA);
        }
    }
    __syncthreads();
    for (int i = tid; i < 8192; i += 256) {
        int c = i >> 7, q = i & 127;
        out[nb + (size_t)c*HW + q0 + q] = Os[c*132 + q];
    }
}

// ---------------------------------------------------------------------------
extern "C" void kernel_launch(void* const* d_in, const int* in_sizes, int n_in,
                              void* d_out, int out_size) {
    const float* x     = (const float*)d_in[0];
    const float* h0    = (const float*)d_in[1];
    const float* h1    = (const float*)d_in[2];
    const float* Wq    = (const float*)d_in[3];
    const float* bq    = (const float*)d_in[4];
    const float* gq    = (const float*)d_in[5];
    const float* betaq = (const float*)d_in[6];
    const float* Wk    = (const float*)d_in[7];
    const float* bk    = (const float*)d_in[8];
    const float* gk    = (const float*)d_in[9];
    const float* betak = (const float*)d_in[10];
    const float* Wv    = (const float*)d_in[11];
    const float* bv    = (const float*)d_in[12];
    float* out = (float*)d_out;

    const int proj_smem = 14336 * 4;
    const int prep_smem = 33536 * 2 + 64;
    cudaFuncSetAttribute(proj_kernel, cudaFuncAttributeMaxDynamicSharedMemorySize, proj_smem);
    cudaFuncSetAttribute(prep_kernel, cudaFuncAttributeMaxDynamicSharedMemorySize, prep_smem);
    cudaFuncSetAttribute(attn_kernel, cudaFuncAttributeMaxDynamicSharedMemorySize, ATTN_SMEM);

    proj_kernel<<<512, 256, proj_smem>>>(x, h0, h1, Wq, bq, Wk, bk, Wv, bv);
    stats_kernel<<<128, 256>>>(gq, betaq, gk, betak);
    prep_kernel<<<dim3(32, NB), 256, prep_smem>>>();
    attn_kernel<<<dim3(32, NB), 256, ATTN_SMEM>>>(out);
}

// round 14
// speedup vs baseline: 1.3850x; 1.0425x over previous
#include <cuda_runtime.h>
#include <cuda_fp16.h>
#include <math.h>
#include <cstdint>

#define CH    64
#define HW    4096
#define NB    4
#define CHW   (CH*HW)
#define TOTAL (NB*CHW)
#define GCH   72
#define GSTR  (GCH*HW)        // per-batch stride of padded G

typedef unsigned long long ull;
typedef unsigned int       u32;
typedef unsigned short     u16;

// ------------------------- device scratch ----------------------------------
__device__ __align__(16) float g_yq[TOTAL];   // [n][c][p]
__device__ __align__(16) float g_yk[TOTAL];
__device__ float               g_aff[4*CH];
__device__ __align__(16) u16   g_g16[NB*GSTR]; // gated value fp16 [n][72][p]; ch64=1, 65-71=0
__device__ __align__(16) u16   g_q16h[TOTAL]; // Q'·log2e fp16 hi [n][p][c]
__device__ __align__(16) u16   g_q16l[TOTAL]; // Q'·log2e fp16 lo
__device__ __align__(16) u16   g_k16h[TOTAL]; // K' fp16 hi [n][p][c]
__device__ __align__(16) u16   g_k16l[TOTAL]; // K' fp16 lo

// ------------------------------ helpers ------------------------------------
__device__ __forceinline__ ull pk2(float x, float y) {
    ull r; asm("mov.b64 %0,{%1,%2};" : "=l"(r) : "f"(x), "f"(y)); return r;
}
__device__ __forceinline__ void upk2(ull v, float& x, float& y) {
    asm("mov.b64 {%0,%1},%2;" : "=f"(x), "=f"(y) : "l"(v));
}
__device__ __forceinline__ void fma2(ull& d, ull a, ull b) {
    asm("fma.rn.f32x2 %0,%1,%2,%0;" : "+l"(d) : "l"(a), "l"(b));
}
__device__ __forceinline__ ull add2_(ull a, ull b) {
    ull r; asm("add.rn.f32x2 %0,%1,%2;" : "=l"(r) : "l"(a), "l"(b)); return r;
}
__device__ __forceinline__ ull mul2_(ull a, ull b) {
    ull r; asm("mul.rn.f32x2 %0,%1,%2;" : "=l"(r) : "l"(a), "l"(b)); return r;
}
__device__ __forceinline__ ull ld2(const float* p) { return *reinterpret_cast<const ull*>(p); }

// split fp32 pair (a,b) -> fp16x2 hi + fp16x2 lo (low 16 bits = a)
__device__ __forceinline__ void split2h(float a, float b, u32& h2, u32& l2) {
    __half2 h = __floats2half2_rn(a, b);
    float2 f = __half22float2(h);
    __half2 l = __floats2half2_rn(a - f.x, b - f.y);
    h2 = *reinterpret_cast<u32*>(&h);
    l2 = *reinterpret_cast<u32*>(&l);
}
__device__ __forceinline__ u32 pack2h(float a, float b) {
    __half2 h = __floats2half2_rn(a, b);
    return *reinterpret_cast<u32*>(&h);
}
__device__ __forceinline__ u32 ex2h2(u32 x) {
    u32 r; asm("ex2.approx.f16x2 %0, %1;" : "=r"(r) : "r"(x)); return r;
}
__device__ __forceinline__ u32 smem_u32(const void* p) {
    u32 a; asm("{ .reg .u64 t; cvta.to.shared.u64 t, %1; cvt.u32.u64 %0, t; }" : "=r"(a) : "l"(p));
    return a;
}
__device__ __forceinline__ void cpasync16(u32 s, const void* g) {
    asm volatile("cp.async.cg.shared.global [%0], [%1], 16;" :: "r"(s), "l"(g) : "memory");
}
#define CP_COMMIT() asm volatile("cp.async.commit_group;" ::: "memory")
#define CP_WAIT(n)  asm volatile("cp.async.wait_group %0;" :: "n"(n) : "memory")

__device__ __forceinline__ void ldsm4(u32* t, u32 addr) {
    asm volatile("ldmatrix.sync.aligned.m8n8.x4.shared.b16 {%0,%1,%2,%3}, [%4];"
        : "=r"(t[0]), "=r"(t[1]), "=r"(t[2]), "=r"(t[3]) : "r"(addr));
}
__device__ __forceinline__ void ldsm2(u32& a, u32& b, u32 addr) {
    asm volatile("ldmatrix.sync.aligned.m8n8.x2.shared.b16 {%0,%1}, [%2];"
        : "=r"(a), "=r"(b) : "r"(addr));
}
// D += A * B   fp16 in, f32 accum
__device__ __forceinline__ void mma16816h(float* d, const u32* a, u32 b0, u32 b1) {
    asm volatile("mma.sync.aligned.m16n8k16.row.col.f32.f16.f16.f32 "
        "{%0,%1,%2,%3}, {%4,%5,%6,%7}, {%8,%9}, {%0,%1,%2,%3};"
        : "+f"(d[0]), "+f"(d[1]), "+f"(d[2]), "+f"(d[3])
        : "r"(a[0]), "r"(a[1]), "r"(a[2]), "r"(a[3]), "r"(b0), "r"(b1));
}

// ---------------------------------------------------------------------------
// Kernel 1: projections + gated value fp16 (padded layout) + ones/zero channels
// ---------------------------------------------------------------------------
__global__ __launch_bounds__(256)
void proj_kernel(const float* __restrict__ x,
                 const float* __restrict__ h0,
                 const float* __restrict__ h1,
                 const float* __restrict__ Wq, const float* __restrict__ bq,
                 const float* __restrict__ Wk, const float* __restrict__ bk,
                 const float* __restrict__ Wv, const float* __restrict__ bv) {
    extern __shared__ float sm[];
    float* sWq = sm;
    float* sWk = sm + 4096;
    float* sWv = sm + 8192;
    float* xs  = sm + 12288;   // [64][32]

    int tid = threadIdx.x;
    for (int i = tid; i < 4096; i += 256) {
        sWq[i] = Wq[i]; sWk[i] = Wk[i]; sWv[i] = Wv[i];
    }
    int P0 = blockIdx.x * 32;
    int n  = P0 >> 12;
    int p0 = P0 & (HW - 1);
    const float* xb = x + (size_t)n*CHW + p0;
    for (int i = tid; i < 2048; i += 256) {
        int c = i >> 5, pp = i & 31;
        xs[c*32 + pp] = xb[(size_t)c*HW + pp];
    }
    // pad channels of G: ch 64 = 1.0 (fp16 0x3C00), ch 65-71 = 0
    {
        int c = 64 + (tid >> 5), p = tid & 31;
        g_g16[(size_t)n*GSTR + (size_t)c*HW + p0 + p] = (c == 64) ? (u16)0x3C00 : (u16)0;
    }
    __syncthreads();

    int ty = tid >> 4, tx = tid & 15;
    ull aq2[4], ak2[4], av2[4];
    #pragma unroll
    for (int io = 0; io < 4; io++) {
        int o = ty + 16*io;
        aq2[io] = pk2(bq[o], bq[o]);
        ak2[io] = pk2(bk[o], bk[o]);
        av2[io] = pk2(bv[o], bv[o]);
    }
    #pragma unroll 4
    for (int c = 0; c < 64; c++) {
        ull xv = ld2(&xs[c*32 + 2*tx]);
        #pragma unroll
        for (int io = 0; io < 4; io++) {
            int o = ty + 16*io;
            float wqs = sWq[o*64+c], wks = sWk[o*64+c], wvs = sWv[o*64+c];
            fma2(aq2[io], pk2(wqs,wqs), xv);
            fma2(ak2[io], pk2(wks,wks), xv);
            fma2(av2[io], pk2(wvs,wvs), xv);
        }
    }
    size_t base = (size_t)n*CHW + p0;
    #pragma unroll
    for (int io = 0; io < 4; io++) {
        int o = ty + 16*io;
        size_t idx = base + (size_t)o*HW + 2*tx;
        *reinterpret_cast<ull*>(&g_yq[idx]) = aq2[io];
        *reinterpret_cast<ull*>(&g_yk[idx]) = ak2[io];
        ull h0p = *reinterpret_cast<const ull*>(&h0[idx]);
        ull h1p = *reinterpret_cast<const ull*>(&h1[idx]);
        ull gv  = mul2_(add2_(h0p, h1p), av2[io]);
        float ga, gb; upk2(gv, ga, gb);
        size_t gidx = (size_t)n*GSTR + (size_t)o*HW + p0 + 2*tx;
        *reinterpret_cast<u32*>(&g_g16[gidx]) = pack2h(ga, gb);
    }
}

// ---------------------------------------------------------------------------
// Kernel 2: BN stats -> affine coefs (Q coefs pre-scaled by log2 e)
// ---------------------------------------------------------------------------
__global__ __launch_bounds__(256)
void stats_kernel(const float* __restrict__ gq, const float* __restrict__ betaq,
                  const float* __restrict__ gk, const float* __restrict__ betak) {
    int ch    = blockIdx.x & 63;
    int which = blockIdx.x >> 6;
    const float* y = which ? g_yk : g_yq;
    int tid = threadIdx.x;
    float s = 0.f, sq = 0.f;
    for (int n = 0; n < NB; n++) {
        const float4* row = (const float4*)(y + (size_t)n*CHW + (size_t)ch*HW);
        for (int p = tid; p < 1024; p += 256) {
            float4 v = row[p];
            s  += (v.x + v.y) + (v.z + v.w);
            sq += (v.x*v.x + v.y*v.y) + (v.z*v.z + v.w*v.w);
        }
    }
    __shared__ float rs[256], rq[256];
    rs[tid] = s; rq[tid] = sq;
    __syncthreads();
    for (int st = 128; st > 0; st >>= 1) {
        if (tid < st) { rs[tid] += rs[tid+st]; rq[tid] += rq[tid+st]; }
        __syncthreads();
    }
    if (tid == 0) {
        const float invn = 1.0f / (NB * HW);
        float mean = rs[0] * invn;
        float var  = rq[0] * invn - mean*mean;
        float g = which ? gk[ch]    : gq[ch];
        float b = which ? betak[ch] : betaq[ch];
        float a = g * rsqrtf(var + 1e-5f);
        float sc = which ? 1.0f : 1.44269504f;   // fold log2e into Q path
        g_aff[which*128 + ch]      = a * sc;
        g_aff[which*128 + 64 + ch] = (b - mean*a) * sc;
    }
}

// ---------------------------------------------------------------------------
// Kernel 2.5: BN affine + relu; Q,K -> fp16 hi/lo; transpose to [n][p][c]
// ---------------------------------------------------------------------------
__global__ __launch_bounds__(256)
void prep_kernel() {
    extern __shared__ u16 sp[];
    u16* sQh = sp;
    u16* sQl = sp + 8384;
    u16* sKh = sp + 16768;
    u16* sKl = sp + 25152;
    int tid = threadIdx.x;
    int n = blockIdx.y, p0 = blockIdx.x * 128;
    size_t nb = (size_t)n*CHW;

    for (int i = tid; i < 2048; i += 256) {
        int c = i >> 5, j = i & 31;
        float4 vq = *(const float4*)&g_yq[nb + (size_t)c*HW + p0 + 4*j];
        float4 vk = *(const float4*)&g_yk[nb + (size_t)c*HW + p0 + 4*j];
        float aq = g_aff[c], bqv = g_aff[64+c];
        float ak = g_aff[128+c], bkv = g_aff[192+c];
        float q0f = fmaxf(0.f, aq*vq.x + bqv), q1f = fmaxf(0.f, aq*vq.y + bqv);
        float q2f = fmaxf(0.f, aq*vq.z + bqv), q3f = fmaxf(0.f, aq*vq.w + bqv);
        float k0f = fmaxf(0.f, ak*vk.x + bkv), k1f = fmaxf(0.f, ak*vk.y + bkv);
        float k2f = fmaxf(0.f, ak*vk.z + bkv), k3f = fmaxf(0.f, ak*vk.w + bkv);
        int base = c*131 + 4*j;
        u32 h2, l2;
        split2h(q0f, q1f, h2, l2);
        sQh[base]   = (u16)h2; sQh[base+1] = (u16)(h2>>16);
        sQl[base]   = (u16)l2; sQl[base+1] = (u16)(l2>>16);
        split2h(q2f, q3f, h2, l2);
        sQh[base+2] = (u16)h2; sQh[base+3] = (u16)(h2>>16);
        sQl[base+2] = (u16)l2; sQl[base+3] = (u16)(l2>>16);
        split2h(k0f, k1f, h2, l2);
        sKh[base]   = (u16)h2; sKh[base+1] = (u16)(h2>>16);
        sKl[base]   = (u16)l2; sKl[base+1] = (u16)(l2>>16);
        split2h(k2f, k3f, h2, l2);
        sKh[base+2] = (u16)h2; sKh[base+3] = (u16)(h2>>16);
        sKl[base+2] = (u16)l2; sKl[base+3] = (u16)(l2>>16);
    }
    __syncthreads();

    u32* oqh = (u32*)g_q16h; u32* oql = (u32*)g_q16l;
    u32* okh = (u32*)g_k16h; u32* okl = (u32*)g_k16l;
    for (int i = tid; i < 4096; i += 256) {
        int p = i >> 5, c2 = i & 31;
        u32 idx = (u32)(n*4096 + p0 + p)*32 + c2;
        u32 a, b;
        a = sQh[(2*c2)*131 + p]; b = sQh[(2*c2+1)*131 + p]; oqh[idx] = a | (b<<16);
        a = sQl[(2*c2)*131 + p]; b = sQl[(2*c2+1)*131 + p]; oql[idx] = a | (b<<16);
        a = sKh[(2*c2)*131 + p]; b = sKh[(2*c2+1)*131 + p]; okh[idx] = a | (b<<16);
        a = sKl[(2*c2)*131 + p]; b = sKl[(2*c2+1)*131 + p]; okl[idx] = a | (b<<16);
    }
}

// ---------------------------------------------------------------------------
// Kernel 3: flash attention. S: fp16 3-pass, log2 domain.
// ctx: fp16 1-pass + ones-channel -> denominator via tensor core.
// P via ex2.approx.f16x2. 4 smem buffers, cross-tile pipelining.
// Buffer (28800 B): Kh[64key][72u16]@0, Kl@9216, G[72c][72u16]@18432
// ---------------------------------------------------------------------------
#define KLO_OFF 9216u
#define G_OFF   18432u
#define BUFSZ   28800u
#define ATTN_SMEM (4*28800)

__device__ __forceinline__ void load_kg(u32 buf, int n, int k0, int tid) {
    const u16* kh = g_k16h + (size_t)(n*4096 + k0)*64;
    const u16* kl = g_k16l + (size_t)(n*4096 + k0)*64;
    const u16* gg = g_g16 + (size_t)n*GSTR + k0;
    #pragma unroll
    for (int ii = 0; ii < 2; ii++) {
        int i = tid + ii*256;
        int row = i >> 3, seg = i & 7;
        u32 sk = buf + (u32)row*144u + (u32)seg*16u;
        cpasync16(sk,           kh + row*64 + seg*8);
        cpasync16(sk + KLO_OFF, kl + row*64 + seg*8);
    }
    for (int i = tid; i < 576; i += 256) {
        int row = i >> 3, seg = i & 7;
        cpasync16(buf + G_OFF + (u32)row*144u + (u32)seg*16u,
                  gg + (size_t)row*HW + seg*8);
    }
}

__global__ __launch_bounds__(256, 1)
void attn_kernel(float* __restrict__ out) {
    extern __shared__ char smc[];
    u32 sb = smem_u32(smc);
    const int tid = threadIdx.x;
    const int w = tid >> 5, lane = tid & 31;
    const int n = blockIdx.y, q0 = blockIdx.x * 128;
    const size_t nb = (size_t)n * CHW;
    const int r0 = lane >> 2, cb = (lane & 3) * 2;

    // ---- Q fp16 fragments straight from gmem ----
    u32 qh[4][4], ql[4][4];
    {
        const u16* qbh = g_q16h + (size_t)(n*4096 + q0 + w*16)*64;
        const u16* qbl = g_q16l + (size_t)(n*4096 + q0 + w*16)*64;
        #pragma unroll
        for (int kc = 0; kc < 4; kc++)
            #pragma unroll
            for (int r = 0; r < 4; r++) {
                int off = (r0 + (r & 1)*8)*64 + cb + (r >> 1)*8 + kc*16;
                qh[kc][r] = *(const u32*)(qbh + off);
                ql[kc][r] = *(const u32*)(qbl + off);
            }
    }

    float ctx[8][4];
    #pragma unroll
    for (int t = 0; t < 8; t++)
        #pragma unroll
        for (int r = 0; r < 4; r++) ctx[t][r] = 0.f;
    float lacc[4] = {0.f, 0.f, 0.f, 0.f};   // ones-channel accumulator (col64 -> l)
    float mA = -1e30f, mB = -1e30f;
    float scA = 0.f, scB = 0.f;
    float sacc[8][4];
    u32 pf0[4][4], pf1[4][4];

    const u32 lm_row = (u32)(lane & 15);
    const u32 lm_hi  = (u32)(lane >> 4) * 16u;
    const u32 lm_l   = (u32)(lane & 7)*144u + (u32)((lane >> 3) & 1)*16u;  // l-block ldsm2

    // ---- S = Q·K^T fp16 3-pass (log2 domain), 4 chains ----
    auto do_smma = [&](u32 cur) {
        #pragma unroll
        for (int t = 0; t < 8; t++)
            #pragma unroll
            for (int r = 0; r < 4; r++) sacc[t][r] = 0.f;
        #pragma unroll
        for (int ntp = 0; ntp < 2; ntp++) {
            u32 ra0 = cur + ((2*ntp)*16u   + lm_row)*144u + lm_hi;
            u32 ra1 = cur + ((2*ntp+1)*16u + lm_row)*144u + lm_hi;
            float* s0 = sacc[4*ntp];
            float* s1 = sacc[4*ntp+1];
            float* s2 = sacc[4*ntp+2];
            float* s3 = sacc[4*ntp+3];
            #pragma unroll
            for (int kc = 0; kc < 4; kc++) {
                u32 b0h[4], b0l[4], b1h[4], b1l[4];
                ldsm4(b0h, ra0 + kc*32u);
                ldsm4(b1h, ra1 + kc*32u);
                ldsm4(b0l, ra0 + KLO_OFF + kc*32u);
                ldsm4(b1l, ra1 + KLO_OFF + kc*32u);
                mma16816h(s0, qh[kc], b0h[0], b0h[2]);
                mma16816h(s1, qh[kc], b0h[1], b0h[3]);
                mma16816h(s2, qh[kc], b1h[0], b1h[2]);
                mma16816h(s3, qh[kc], b1h[1], b1h[3]);
                mma16816h(s0, ql[kc], b0h[0], b0h[2]);
                mma16816h(s1, ql[kc], b0h[1], b0h[3]);
                mma16816h(s2, ql[kc], b1h[0], b1h[2]);
                mma16816h(s3, ql[kc], b1h[1], b1h[3]);
                mma16816h(s0, qh[kc], b0l[0], b0l[2]);
                mma16816h(s1, qh[kc], b0l[1], b0l[3]);
                mma16816h(s2, qh[kc], b1l[0], b1l[2]);
                mma16816h(s3, qh[kc], b1l[1], b1l[3]);
            }
        }
    };

    // ---- online row-max (log2 domain) ----
    auto rowmax = [&]() {
        float tA = sacc[0][0], tB = sacc[0][2];
        #pragma unroll
        for (int t = 0; t < 8; t++) {
            tA = fmaxf(tA, fmaxf(sacc[t][0], sacc[t][1]));
            tB = fmaxf(tB, fmaxf(sacc[t][2], sacc[t][3]));
        }
        tA = fmaxf(tA, __shfl_xor_sync(0xffffffffu, tA, 1));
        tA = fmaxf(tA, __shfl_xor_sync(0xffffffffu, tA, 2));
        tB = fmaxf(tB, __shfl_xor_sync(0xffffffffu, tB, 1));
        tB = fmaxf(tB, __shfl_xor_sync(0xffffffffu, tB, 2));
        float nmA = fmaxf(mA, tA), nmB = fmaxf(mB, tB);
        scA = exp2f(mA - nmA); scB = exp2f(mB - nmB);
        mA = nmA; mB = nmB;
    };

    // ---- epilogue piece: sacc[chunk] -> fp16 P via ex2.f16x2 ----
    auto epi_piece = [&](int chunk, u32 (&pfC)[4][4]) {
        float x0 = sacc[chunk][0] - mA;
        float x1 = sacc[chunk][1] - mA;
        float x2 = sacc[chunk][2] - mB;
        float x3 = sacc[chunk][3] - mB;
        int j2 = chunk >> 1, half = chunk & 1;
        pfC[j2][2*half]   = ex2h2(pack2h(x0, x1));
        pfC[j2][2*half+1] = ex2h2(pack2h(x2, x3));
    };

    // ---- ctx(prev) fp16 1-pass + l-block, interleaved with epilogue(cur) ----
    auto do_ctx_epi = [&](u32 gslot, u32 (&pfP)[4][4], u32 (&pfC)[4][4]) {
        #pragma unroll
        for (int cgp = 0; cgp < 2; cgp++) {
            u32 ra0 = gslot + G_OFF + ((2*cgp)*16u   + lm_row)*144u + lm_hi;
            u32 ra1 = gslot + G_OFF + ((2*cgp+1)*16u + lm_row)*144u + lm_hi;
            float* c0 = ctx[4*cgp];
            float* c1 = ctx[4*cgp+1];
            float* c2 = ctx[4*cgp+2];
            float* c3 = ctx[4*cgp+3];
            #pragma unroll
            for (int j = 0; j < 4; j++) {
                u32 b0[4], b1[4];
                ldsm4(b0, ra0 + j*32u);
                ldsm4(b1, ra1 + j*32u);
                mma16816h(c0, pfP[j], b0[0], b0[2]);
                mma16816h(c1, pfP[j], b0[1], b0[3]);
                mma16816h(c2, pfP[j], b1[0], b1[2]);
                mma16816h(c3, pfP[j], b1[1], b1[3]);
                epi_piece(cgp*4 + j, pfC);
            }
        }
        u32 la = gslot + G_OFF + 64u*144u + lm_l;
        #pragma unroll
        for (int j = 0; j < 4; j++) {
            u32 m0, m1;
            ldsm2(m0, m1, la + j*32u);
            mma16816h(lacc, pfP[j], m0, m1);
        }
    };

    auto do_ctx = [&](u32 gslot, u32 (&pfP)[4][4]) {
        #pragma unroll
        for (int cgp = 0; cgp < 2; cgp++) {
            u32 ra0 = gslot + G_OFF + ((2*cgp)*16u   + lm_row)*144u + lm_hi;
            u32 ra1 = gslot + G_OFF + ((2*cgp+1)*16u + lm_row)*144u + lm_hi;
            float* c0 = ctx[4*cgp];
            float* c1 = ctx[4*cgp+1];
            float* c2 = ctx[4*cgp+2];
            float* c3 = ctx[4*cgp+3];
            #pragma unroll
            for (int j = 0; j < 4; j++) {
                u32 b0[4], b1[4];
                ldsm4(b0, ra0 + j*32u);
                ldsm4(b1, ra1 + j*32u);
                mma16816h(c0, pfP[j], b0[0], b0[2]);
                mma16816h(c1, pfP[j], b0[1], b0[3]);
                mma16816h(c2, pfP[j], b1[0], b1[2]);
                mma16816h(c3, pfP[j], b1[1], b1[3]);
            }
        }
        u32 la = gslot + G_OFF + 64u*144u + lm_l;
        #pragma unroll
        for (int j = 0; j < 4; j++) {
            u32 m0, m1;
            ldsm2(m0, m1, la + j*32u);
            mma16816h(lacc, pfP[j], m0, m1);
        }
    };

    // rescale ctx (and l accumulator) to the new max scale
    auto rescale = [&]() {
        #pragma unroll
        for (int t = 0; t < 8; t++) {
            ctx[t][0] *= scA; ctx[t][1] *= scA;
            ctx[t][2] *= scB; ctx[t][3] *= scB;
        }
        lacc[0] *= scA; lacc[2] *= scB;
    };

    // prologue: load tiles 0,1; S(0); rowmax; epilogue(0) -> pf0
    load_kg(sb,          n, 0,  tid); CP_COMMIT();
    load_kg(sb + BUFSZ,  n, 64, tid); CP_COMMIT();
    CP_WAIT(1);
    __syncthreads();
    do_smma(sb);
    rowmax();
    #pragma unroll
    for (int chunk = 0; chunk < 8; chunk++) epi_piece(chunk, pf0);
    rescale();

    auto body = [&](int t, u32 (&pfP)[4][4], u32 (&pfC)[4][4]) {
        if (t < 63) {
            load_kg(sb + (u32)((t + 1) & 3) * BUFSZ, n, (t + 1) * 64, tid);
            CP_COMMIT();
            CP_WAIT(1);
        } else {
            CP_WAIT(0);
        }
        __syncthreads();
        do_smma(sb + (u32)(t & 3) * BUFSZ);
        rowmax();
        do_ctx_epi(sb + (u32)((t - 1) & 3) * BUFSZ, pfP, pfC);
        rescale();
    };

    for (int t = 1; t + 1 < 64; t += 2) {
        body(t,     pf0, pf1);
        body(t + 1, pf1, pf0);
    }
    body(63, pf0, pf1);
    do_ctx(sb + 3u * BUFSZ, pf1);   // drain ctx(63): G slot 63&3=3

    // ---- finalize: l from tensor-core accumulator (quad leader holds col 64)
    float lA = __shfl_sync(0xffffffffu, lacc[0], lane & ~3);
    float lB = __shfl_sync(0xffffffffu, lacc[2], lane & ~3);
    float invA = 1.0f / lA, invB = 1.0f / lB;

    // Os overlaps slots 0/1 only; drain reads slot 3 — disjoint.
    float* Os = (float*)smc;   // [64][132]
    #pragma unroll
    for (int t = 0; t < 8; t++) {
        #pragma unroll
        for (int r = 0; r < 4; r++) {
            int row = r0 + 8*(r >> 1);
            int c   = t*8 + cb + (r & 1);
            Os[c*132 + w*16 + row] = ctx[t][r] * ((r >> 1) ? invB : invA);
        }
    }
    __syncthreads();
    for (int i = tid; i < 8192; i += 256) {
        int c = i >> 7, q = i & 127;
        out[nb + (size_t)c*HW + q0 + q] = Os[c*132 + q];
    }
}

// ---------------------------------------------------------------------------
extern "C" void kernel_launch(void* const* d_in, const int* in_sizes, int n_in,
                              void* d_out, int out_size) {
    const float* x     = (const float*)d_in[0];
    const float* h0    = (const float*)d_in[1];
    const float* h1    = (const float*)d_in[2];
    const float* Wq    = (const float*)d_in[3];
    const float* bq    = (const float*)d_in[4];
    const float* gq    = (const float*)d_in[5];
    const float* betaq = (const float*)d_in[6];
    const float* Wk    = (const float*)d_in[7];
    const float* bk    = (const float*)d_in[8];
    const float* gk    = (const float*)d_in[9];
    const float* betak = (const float*)d_in[10];
    const float* Wv    = (const float*)d_in[11];
    const float* bv    = (const float*)d_in[12];
    float* out = (float*)d_out;

    const int proj_smem = 14336 * 4;
    const int prep_smem = 33536 * 2 + 64;
    cudaFuncSetAttribute(proj_kernel, cudaFuncAttributeMaxDynamicSharedMemorySize, proj_smem);
    cudaFuncSetAttribute(prep_kernel, cudaFuncAttributeMaxDynamicSharedMemorySize, prep_smem);
    cudaFuncSetAttribute(attn_kernel, cudaFuncAttributeMaxDynamicSharedMemorySize, ATTN_SMEM);

    proj_kernel<<<512, 256, proj_smem>>>(x, h0, h1, Wq, bq, Wk, bk, Wv, bv);
    stats_kernel<<<128, 256>>>(gq, betaq, gk, betak);
    prep_kernel<<<dim3(32, NB), 256, prep_smem>>>();
    attn_kernel<<<dim3(32, NB), 256, ATTN_SMEM>>>(out);
}